// round 1
// baseline (speedup 1.0000x reference)
#include <cuda_runtime.h>
#include <math.h>

#define NN 100000
#define EE 1600000
#define GG 256
#define NB_SCAN 98   /* ceil(NN/1024) */

// ---------------- scratch (device globals; no allocation allowed) ----------
__device__ float g_x[NN * 128];
__device__ float g_y[NN * 128];
__device__ float g_h[NN * 128];
__device__ float g_hg[NN * 128];
__device__ int   g_cnt[NN];
__device__ int   g_offs[NN];
__device__ int   g_cursor[NN];
__device__ int   g_csrc[EE];
__device__ float g_dis[NN];
__device__ float g_an_src[NN * 4];
__device__ float g_an_dst[NN * 4];
__device__ float g_bnsum[128];
__device__ float g_bnsq[128];
__device__ float g_bnscale[128];
__device__ float g_bnshift[128];
__device__ int   g_bsum[128];
__device__ float g_pool[GG * 64];
__device__ float g_pcnt[GG];

__device__ __forceinline__ float lrelu(float v) { return v > 0.f ? v : 0.2f * v; }

// ---------------- init / CSR build ----------------------------------------
__global__ void zero_init() {
    int i = blockIdx.x * blockDim.x + threadIdx.x;
    int stride = gridDim.x * blockDim.x;
    for (int t = i; t < NN; t += stride) { g_cnt[t] = 0; g_cursor[t] = 0; }
    for (int t = i; t < GG * 64; t += stride) g_pool[t] = 0.f;
    for (int t = i; t < GG; t += stride) g_pcnt[t] = 0.f;
}

__global__ void hist_k(const int* __restrict__ col) {
    int i = blockIdx.x * blockDim.x + threadIdx.x;
    for (int e = i; e < EE; e += gridDim.x * blockDim.x)
        atomicAdd(&g_cnt[col[e]], 1);
}

__global__ void scan1() {
    __shared__ int s[1024];
    int t = threadIdx.x;
    int gi = blockIdx.x * 1024 + t;
    int v = (gi < NN) ? g_cnt[gi] : 0;
    s[t] = v;
    for (int off = 1; off < 1024; off <<= 1) {
        __syncthreads();
        int u = (t >= off) ? s[t - off] : 0;
        __syncthreads();
        s[t] += u;
    }
    if (gi < NN) g_offs[gi] = s[t] - v;   // exclusive scan within chunk
    if (t == 1023) g_bsum[blockIdx.x] = s[1023];
}

__global__ void scan2() {
    int run = 0;
    for (int b = 0; b < NB_SCAN; b++) { int t = g_bsum[b]; g_bsum[b] = run; run += t; }
}

__global__ void scan3() {
    int gi = blockIdx.x * 1024 + threadIdx.x;
    if (gi < NN) g_offs[gi] += g_bsum[blockIdx.x];
}

__global__ void dis_k() {
    int i = blockIdx.x * blockDim.x + threadIdx.x;
    if (i < NN) g_dis[i] = rsqrtf((float)(g_cnt[i] + 1));  // +1 self loop
}

__global__ void scatter_k(const int* __restrict__ row, const int* __restrict__ col) {
    int i = blockIdx.x * blockDim.x + threadIdx.x;
    for (int e = i; e < EE; e += gridDim.x * blockDim.x) {
        int c = col[e];
        int pos = g_offs[c] + atomicAdd(&g_cursor[c], 1);
        g_csrc[pos] = row[e];
    }
}

// ---------------- GEMM: out[n,dout] = A[n,din] @ W[din,dout] ---------------
__global__ void gemm_k(const float* __restrict__ A, const float* __restrict__ W,
                       float* __restrict__ out, int n, int din, int dout) {
    __shared__ float As[16][68];
    __shared__ float Bs[16][68];
    int tid = threadIdx.x;
    int row0 = blockIdx.x * 64;
    int col0 = blockIdx.y * 64;
    int tx = tid & 15, ty = tid >> 4;
    float acc[4][4];
#pragma unroll
    for (int i = 0; i < 4; i++)
#pragma unroll
        for (int j = 0; j < 4; j++) acc[i][j] = 0.f;

    for (int k0 = 0; k0 < din; k0 += 16) {
#pragma unroll
        for (int i = 0; i < 4; i++) {
            int idx = tid + i * 256;
            int k = idx & 15, m = idx >> 4;
            int r = row0 + m, kk = k0 + k;
            As[k][m] = (r < n && kk < din) ? A[(size_t)r * din + kk] : 0.f;
        }
#pragma unroll
        for (int i = 0; i < 4; i++) {
            int idx = tid + i * 256;
            int nn = idx & 63, k = idx >> 6;
            int kk = k0 + k;
            Bs[k][nn] = (kk < din) ? W[(size_t)kk * dout + col0 + nn] : 0.f;
        }
        __syncthreads();
#pragma unroll
        for (int k = 0; k < 16; k++) {
            float a[4], b[4];
#pragma unroll
            for (int i = 0; i < 4; i++) a[i] = As[k][ty * 4 + i];
#pragma unroll
            for (int j = 0; j < 4; j++) b[j] = Bs[k][tx * 4 + j];
#pragma unroll
            for (int i = 0; i < 4; i++)
#pragma unroll
                for (int j = 0; j < 4; j++) acc[i][j] += a[i] * b[j];
        }
        __syncthreads();
    }
#pragma unroll
    for (int i = 0; i < 4; i++) {
        int r = row0 + ty * 4 + i;
        if (r < n) {
#pragma unroll
            for (int j = 0; j < 4; j++)
                out[(size_t)r * dout + col0 + tx * 4 + j] = acc[i][j];
        }
    }
}

// ---------------- GCN aggregation (warp per node, CSR pull) ----------------
__global__ void gcn_agg(const float* __restrict__ h, const float* __restrict__ bias,
                        float* __restrict__ y, int dout) {
    int warp = (blockIdx.x * blockDim.x + threadIdx.x) >> 5;
    int lane = threadIdx.x & 31;
    if (warp >= NN) return;
    int i = warp;
    int chunks = dout >> 5;
    float di = g_dis[i];
    float acc[4] = {0.f, 0.f, 0.f, 0.f};
    float ws = di * di;  // self loop norm
#pragma unroll
    for (int cc = 0; cc < 4; cc++)
        if (cc < chunks) acc[cc] = h[(size_t)i * dout + cc * 32 + lane] * ws;
    int s = g_offs[i], cnt = g_cnt[i];
    for (int e = s; e < s + cnt; e++) {
        int j = g_csrc[e];
        float w = g_dis[j] * di;
#pragma unroll
        for (int cc = 0; cc < 4; cc++)
            if (cc < chunks) acc[cc] += h[(size_t)j * dout + cc * 32 + lane] * w;
    }
#pragma unroll
    for (int cc = 0; cc < 4; cc++)
        if (cc < chunks)
            y[(size_t)i * dout + cc * 32 + lane] = acc[cc] + bias[cc * 32 + lane];
}

// ---------------- BatchNorm ------------------------------------------------
__global__ void zero_bn() {
    int t = threadIdx.x;
    g_bnsum[t] = 0.f;
    g_bnsq[t] = 0.f;
}

__global__ void bn_reduce(const float* __restrict__ x, int dout) {
    int col = threadIdx.x;  // blockDim.x == dout
    float s = 0.f, q = 0.f;
    for (int r = blockIdx.x; r < NN; r += gridDim.x) {
        float v = x[(size_t)r * dout + col];
        s += v;
        q += v * v;
    }
    atomicAdd(&g_bnsum[col], s);
    atomicAdd(&g_bnsq[col], q);
}

__global__ void bn_finalize(const float* __restrict__ g, const float* __restrict__ b, int dout) {
    int c = threadIdx.x;
    if (c >= dout) return;
    float mean = g_bnsum[c] * (1.f / NN);
    float var = g_bnsq[c] * (1.f / NN) - mean * mean;
    float istd = rsqrtf(var + 1e-5f);
    float sc = g[c] * istd;
    g_bnscale[c] = sc;
    g_bnshift[c] = b[c] - mean * sc;
}

__global__ void bn_apply(float* __restrict__ x, int dout, int leaky) {
    size_t total = (size_t)NN * dout;
    size_t i = (size_t)blockIdx.x * blockDim.x + threadIdx.x;
    size_t stride = (size_t)gridDim.x * blockDim.x;
    int mask = dout - 1;  // dout is a power of two
    for (size_t t = i; t < total; t += stride) {
        int col = (int)(t & mask);
        float v = x[t] * g_bnscale[col] + g_bnshift[col];
        if (leaky) v = lrelu(v);
        x[t] = v;
    }
}

// ---------------- GAT ------------------------------------------------------
__global__ void attn_coef(const float* __restrict__ hg, const float* __restrict__ av_src,
                          const float* __restrict__ av_dst, int dout) {
    int warp = (blockIdx.x * blockDim.x + threadIdx.x) >> 5;
    int lane = threadIdx.x & 31;
    if (warp >= NN) return;
    int i = warp;
    int C = dout >> 2;       // channels per head
    int chunks = dout >> 5;
#pragma unroll
    for (int cc = 0; cc < 4; cc++) {
        if (cc < chunks) {
            int col = cc * 32 + lane;
            float hv = hg[(size_t)i * dout + col];
            float v1 = hv * av_src[col];
            float v2 = hv * av_dst[col];
            for (int off = C >> 1; off > 0; off >>= 1) {
                v1 += __shfl_down_sync(0xffffffffu, v1, off);
                v2 += __shfl_down_sync(0xffffffffu, v2, off);
            }
            if ((lane % C) == 0) {
                int hh = col / C;
                g_an_src[i * 4 + hh] = v1;
                g_an_dst[i * 4 + hh] = v2;
            }
        }
    }
}

__global__ void gat_agg(const float* __restrict__ hg, const float* __restrict__ yres,
                        const float* __restrict__ bias, float* __restrict__ xout,
                        int dout, int leaky) {
    int warp = (blockIdx.x * blockDim.x + threadIdx.x) >> 5;
    int lane = threadIdx.x & 31;
    if (warp >= NN) return;
    int i = warp;
    int C = dout >> 2;
    int chunks = dout >> 5;
    float4 asi = *(const float4*)&g_an_src[i * 4];
    float4 adi = *(const float4*)&g_an_dst[i * 4];
    float e0 = lrelu(asi.x + adi.x);
    float e1 = lrelu(asi.y + adi.y);
    float e2 = lrelu(asi.z + adi.z);
    float e3 = lrelu(asi.w + adi.w);
    float m0 = e0, m1 = e1, m2 = e2, m3 = e3;
    int s = g_offs[i], cnt = g_cnt[i];
    // pass 1: max over incoming edge logits (lanes strided over edges)
    for (int e = s + lane; e < s + cnt; e += 32) {
        int j = g_csrc[e];
        float4 aj = *(const float4*)&g_an_src[j * 4];
        m0 = fmaxf(m0, lrelu(aj.x + adi.x));
        m1 = fmaxf(m1, lrelu(aj.y + adi.y));
        m2 = fmaxf(m2, lrelu(aj.z + adi.z));
        m3 = fmaxf(m3, lrelu(aj.w + adi.w));
    }
#pragma unroll
    for (int off = 16; off > 0; off >>= 1) {
        m0 = fmaxf(m0, __shfl_xor_sync(0xffffffffu, m0, off));
        m1 = fmaxf(m1, __shfl_xor_sync(0xffffffffu, m1, off));
        m2 = fmaxf(m2, __shfl_xor_sync(0xffffffffu, m2, off));
        m3 = fmaxf(m3, __shfl_xor_sync(0xffffffffu, m3, off));
    }
    // self edge
    float p0 = __expf(e0 - m0), p1 = __expf(e1 - m1);
    float p2 = __expf(e2 - m2), p3 = __expf(e3 - m3);
    float den0 = p0, den1 = p1, den2 = p2, den3 = p3;
    int hh[4];
    float acc[4];
#pragma unroll
    for (int cc = 0; cc < 4; cc++) {
        hh[cc] = (cc * 32 + lane) / C;
        acc[cc] = 0.f;
    }
#pragma unroll
    for (int cc = 0; cc < 4; cc++)
        if (cc < chunks) {
            float p = hh[cc] == 0 ? p0 : hh[cc] == 1 ? p1 : hh[cc] == 2 ? p2 : p3;
            acc[cc] = hg[(size_t)i * dout + cc * 32 + lane] * p;
        }
    // pass 2: weighted gather (full warp per edge; scalar logits broadcast)
    for (int e = s; e < s + cnt; e++) {
        int j = g_csrc[e];
        float4 aj = *(const float4*)&g_an_src[j * 4];
        float q0 = __expf(lrelu(aj.x + adi.x) - m0);
        float q1 = __expf(lrelu(aj.y + adi.y) - m1);
        float q2 = __expf(lrelu(aj.z + adi.z) - m2);
        float q3 = __expf(lrelu(aj.w + adi.w) - m3);
        den0 += q0; den1 += q1; den2 += q2; den3 += q3;
#pragma unroll
        for (int cc = 0; cc < 4; cc++)
            if (cc < chunks) {
                float p = hh[cc] == 0 ? q0 : hh[cc] == 1 ? q1 : hh[cc] == 2 ? q2 : q3;
                acc[cc] += hg[(size_t)j * dout + cc * 32 + lane] * p;
            }
    }
#pragma unroll
    for (int cc = 0; cc < 4; cc++)
        if (cc < chunks) {
            float d = hh[cc] == 0 ? den0 : hh[cc] == 1 ? den1 : hh[cc] == 2 ? den2 : den3;
            int col = cc * 32 + lane;
            float v = acc[cc] / d + bias[col] + yres[(size_t)i * dout + col];
            if (leaky) v = lrelu(v);
            xout[(size_t)i * dout + col] = v;
        }
}

// ---------------- pooling --------------------------------------------------
__global__ void pool_acc(const float* __restrict__ x, const int* __restrict__ batch) {
    size_t total = (size_t)NN * 64;
    size_t i = (size_t)blockIdx.x * blockDim.x + threadIdx.x;
    size_t stride = (size_t)gridDim.x * blockDim.x;
    for (size_t t = i; t < total; t += stride) {
        int node = (int)(t >> 6);
        int c = (int)(t & 63);
        atomicAdd(&g_pool[batch[node] * 64 + c], x[t]);
    }
}

__global__ void pool_cnt_k(const int* __restrict__ batch) {
    int i = blockIdx.x * blockDim.x + threadIdx.x;
    if (i < NN) atomicAdd(&g_pcnt[batch[i]], 1.f);
}

__global__ void pool_fin(float* __restrict__ out) {
    int i = blockIdx.x * blockDim.x + threadIdx.x;
    if (i < GG * 64) {
        int g = i >> 6;
        out[i] = g_pool[i] / fmaxf(g_pcnt[g], 1.f);
    }
}

// ---------------- host orchestration --------------------------------------
extern "C" void kernel_launch(void* const* d_in, const int* in_sizes, int n_in,
                              void* d_out, int out_size) {
    const float* x_in = (const float*)d_in[0];
    const int* ei = (const int*)d_in[1];
    const int* batch = (const int*)d_in[2];

    const float* gcn_w[4] = {(const float*)d_in[3], (const float*)d_in[7],
                             (const float*)d_in[11], (const float*)d_in[15]};
    const float* gcn_b[4] = {(const float*)d_in[4], (const float*)d_in[8],
                             (const float*)d_in[12], (const float*)d_in[16]};
    const float* bn_g[4] = {(const float*)d_in[5], (const float*)d_in[9],
                            (const float*)d_in[13], (const float*)d_in[17]};
    const float* bn_b[4] = {(const float*)d_in[6], (const float*)d_in[10],
                            (const float*)d_in[14], (const float*)d_in[18]};
    const float* gat_w[2] = {(const float*)d_in[19], (const float*)d_in[23]};
    const float* gat_as[2] = {(const float*)d_in[20], (const float*)d_in[24]};
    const float* gat_ad[2] = {(const float*)d_in[21], (const float*)d_in[25]};
    const float* gat_b[2] = {(const float*)d_in[22], (const float*)d_in[26]};

    float *px, *py, *ph, *phg;
    cudaGetSymbolAddress((void**)&px, g_x);
    cudaGetSymbolAddress((void**)&py, g_y);
    cudaGetSymbolAddress((void**)&ph, g_h);
    cudaGetSymbolAddress((void**)&phg, g_hg);

    // ---- per-launch CSR build + init ----
    zero_init<<<256, 256>>>();
    hist_k<<<1024, 256>>>(ei + EE);
    scan1<<<NB_SCAN, 1024>>>();
    scan2<<<1, 1>>>();
    scan3<<<NB_SCAN, 1024>>>();
    dis_k<<<(NN + 255) / 256, 256>>>();
    scatter_k<<<1024, 256>>>(ei, ei + EE);

    const int dims[5] = {16, 64, 128, 128, 64};
    const float* cur = x_in;
    int din = 16;
    const int warp_blocks = (NN * 32 + 255) / 256;  // warp-per-node kernels

    for (int i = 0; i < 4; i++) {
        int dout = dims[i + 1];
        dim3 ggrid((NN + 63) / 64, dout / 64);
        gemm_k<<<ggrid, 256>>>(cur, gcn_w[i], ph, NN, din, dout);
        gcn_agg<<<warp_blocks, 256>>>(ph, gcn_b[i], py, dout);
        zero_bn<<<1, 128>>>();
        bn_reduce<<<240, dout>>>(py, dout);
        bn_finalize<<<1, 128>>>(bn_g[i], bn_b[i], dout);
        bn_apply<<<1024, 256>>>(py, dout, (i == 1) ? 1 : 0);
        if (i == 0 || i == 2) {
            int gi = (i == 0) ? 0 : 1;
            dim3 ggrid2((NN + 63) / 64, dout / 64);
            gemm_k<<<ggrid2, 256>>>(py, gat_w[gi], phg, NN, dout, dout);
            attn_coef<<<warp_blocks, 256>>>(phg, gat_as[gi], gat_ad[gi], dout);
            gat_agg<<<warp_blocks, 256>>>(phg, py, gat_b[gi], px, dout, 1);
            cur = px;
        } else {
            cur = py;
        }
        din = dout;
    }

    // ---- global mean pool (final dout = 64) ----
    pool_acc<<<1024, 256>>>(cur, batch);
    pool_cnt_k<<<(NN + 255) / 256, 256>>>(batch);
    pool_fin<<<(GG * 64 + 255) / 256, 256>>>((float*)d_out);
}

// round 2
// speedup vs baseline: 1.2126x; 1.2126x over previous
#include <cuda_runtime.h>
#include <math.h>
#include <mma.h>

using namespace nvcuda;

#define NN 100000
#define NPAD 100032            /* 1563 * 64 */
#define EE 1600000
#define GG 256
#define NB_SCAN 98             /* ceil(NN/1024) */

// ---------------- scratch (device globals; no allocation allowed) ----------
__device__ float g_x[NPAD * 128];
__device__ float g_y[NPAD * 128];
__device__ float g_h[NPAD * 128];
__device__ float g_hg[NPAD * 128];
__device__ int   g_cnt[NN];
__device__ int   g_offs[NN];
__device__ int   g_cursor[NN];
__device__ int   g_csrc[EE];
__device__ float g_dis[NN];
__device__ float g_an_src[NN * 4];
__device__ float g_an_dst[NN * 4];
__device__ float g_bnsum[4][128];
__device__ float g_bnsq[4][128];
__device__ float g_bnscale[128];
__device__ float g_bnshift[128];
__device__ int   g_bsum[128];
__device__ float g_pool[GG * 64];
__device__ float g_pcnt[GG];

__device__ __forceinline__ float lrelu(float v) { return v > 0.f ? v : 0.2f * v; }

// ---------------- init / CSR build ----------------------------------------
__global__ void zero_init() {
    int i = blockIdx.x * blockDim.x + threadIdx.x;
    int stride = gridDim.x * blockDim.x;
    for (int t = i; t < NN; t += stride) { g_cnt[t] = 0; g_cursor[t] = 0; }
    for (int t = i; t < GG * 64; t += stride) g_pool[t] = 0.f;
    for (int t = i; t < GG; t += stride) g_pcnt[t] = 0.f;
    for (int t = i; t < 4 * 128; t += stride) { (&g_bnsum[0][0])[t] = 0.f; (&g_bnsq[0][0])[t] = 0.f; }
}

__global__ void hist_k(const int* __restrict__ col, const int* __restrict__ batch) {
    int i = blockIdx.x * blockDim.x + threadIdx.x;
    int stride = gridDim.x * blockDim.x;
    for (int e = i; e < EE; e += stride)
        atomicAdd(&g_cnt[col[e]], 1);
    for (int t = i; t < NN; t += stride)
        atomicAdd(&g_pcnt[batch[t]], 1.f);
}

__global__ void scan1() {
    __shared__ int s[1024];
    int t = threadIdx.x;
    int gi = blockIdx.x * 1024 + t;
    int v = (gi < NN) ? g_cnt[gi] : 0;
    s[t] = v;
    for (int off = 1; off < 1024; off <<= 1) {
        __syncthreads();
        int u = (t >= off) ? s[t - off] : 0;
        __syncthreads();
        s[t] += u;
    }
    if (gi < NN) g_offs[gi] = s[t] - v;   // exclusive within chunk
    if (t == 1023) g_bsum[blockIdx.x] = s[1023];
}

__global__ void scan2() {
    // 128-thread parallel exclusive scan of NB_SCAN block sums
    int t = threadIdx.x;
    int lane = t & 31, w = t >> 5;
    int v = (t < NB_SCAN) ? g_bsum[t] : 0;
    int x = v;
#pragma unroll
    for (int off = 1; off < 32; off <<= 1) {
        int u = __shfl_up_sync(0xffffffffu, x, off);
        if (lane >= off) x += u;
    }
    __shared__ int wsum[4];
    if (lane == 31) wsum[w] = x;
    __syncthreads();
    int add = 0;
    for (int i = 0; i < w; i++) add += wsum[i];
    x += add;
    if (t < NB_SCAN) g_bsum[t] = x - v;   // exclusive
}

__global__ void scan3_dis() {
    int gi = blockIdx.x * 1024 + threadIdx.x;
    if (gi < NN) {
        g_offs[gi] += g_bsum[blockIdx.x];
        g_dis[gi] = rsqrtf((float)(g_cnt[gi] + 1));  // +1 self loop
    }
}

__global__ void scatter_k(const int* __restrict__ row, const int* __restrict__ col) {
    int i = blockIdx.x * blockDim.x + threadIdx.x;
    for (int e = i; e < EE; e += gridDim.x * blockDim.x) {
        int c = col[e];
        int pos = g_offs[c] + atomicAdd(&g_cursor[c], 1);
        g_csrc[pos] = row[e];
    }
}

// ---------------- GEMM: 3xTF32 WMMA, out[n,dout] = A[n,din] @ W[din,dout] --
#define BM 64
#define BN 64
#define BK 32

__global__ void gemm_tf32(const float* __restrict__ A, const float* __restrict__ W,
                          float* __restrict__ out, int n, int din, int dout) {
    __shared__ float As[BM][BK + 8];
    __shared__ float Bs[BK][BN + 8];
    int tid = threadIdx.x;
    int warp = tid >> 5;
    int wr = warp >> 1;    // 0..3 -> M offset wr*16
    int wc = warp & 1;     // 0..1 -> N offset wc*32
    int row0 = blockIdx.x * BM;
    int col0 = blockIdx.y * BN;

    wmma::fragment<wmma::accumulator, 16, 16, 8, float> acc[2];
    wmma::fill_fragment(acc[0], 0.f);
    wmma::fill_fragment(acc[1], 0.f);

    for (int k0 = 0; k0 < din; k0 += BK) {
        // A tile: 64 x 32, float4 loads
#pragma unroll
        for (int v = tid; v < BM * 8; v += 256) {
            int r = v >> 3;
            int kk = (v & 7) * 4;
            float4 val = make_float4(0.f, 0.f, 0.f, 0.f);
            int grow = row0 + r, gk = k0 + kk;
            if (grow < n && gk < din)
                val = *(const float4*)(A + (size_t)grow * din + gk);
            *(float4*)&As[r][kk] = val;
        }
        // B tile: 32 x 64, float4 loads
#pragma unroll
        for (int v = tid; v < BK * 16; v += 256) {
            int kk = v >> 4;
            int cc = (v & 15) * 4;
            float4 val = make_float4(0.f, 0.f, 0.f, 0.f);
            int gk = k0 + kk;
            if (gk < din)
                val = *(const float4*)(W + (size_t)gk * dout + col0 + cc);
            *(float4*)&Bs[kk][cc] = val;
        }
        __syncthreads();

#pragma unroll
        for (int ks = 0; ks < BK; ks += 8) {
            wmma::fragment<wmma::matrix_a, 16, 16, 8, wmma::precision::tf32, wmma::row_major> a_hi, a_lo;
            wmma::load_matrix_sync(a_hi, &As[wr * 16][ks], BK + 8);
#pragma unroll
            for (int t = 0; t < a_hi.num_elements; t++) {
                float vv = a_hi.x[t];
                float hi = wmma::__float_to_tf32(vv);
                a_hi.x[t] = hi;
                a_lo.x[t] = wmma::__float_to_tf32(vv - hi);
            }
#pragma unroll
            for (int c = 0; c < 2; c++) {
                wmma::fragment<wmma::matrix_b, 16, 16, 8, wmma::precision::tf32, wmma::row_major> b_hi, b_lo;
                wmma::load_matrix_sync(b_hi, &Bs[ks][wc * 32 + c * 16], BN + 8);
#pragma unroll
                for (int t = 0; t < b_hi.num_elements; t++) {
                    float vv = b_hi.x[t];
                    float hi = wmma::__float_to_tf32(vv);
                    b_hi.x[t] = hi;
                    b_lo.x[t] = wmma::__float_to_tf32(vv - hi);
                }
                wmma::mma_sync(acc[c], a_hi, b_hi, acc[c]);
                wmma::mma_sync(acc[c], a_lo, b_hi, acc[c]);
                wmma::mma_sync(acc[c], a_hi, b_lo, acc[c]);
            }
        }
        __syncthreads();
    }
    // out is oversized scratch (NPAD rows): store unguarded
    int grow = row0 + wr * 16;
#pragma unroll
    for (int c = 0; c < 2; c++)
        wmma::store_matrix_sync(out + (size_t)grow * dout + col0 + wc * 32 + c * 16,
                                acc[c], dout, wmma::mem_row_major);
}

// ---------------- GCN aggregation (warp per node, CSR pull) ----------------
template <int DOUT>
__global__ void gcn_agg(const float* __restrict__ h, const float* __restrict__ bias,
                        float* __restrict__ y) {
    constexpr int CH = DOUT / 32;
    int warp = (blockIdx.x * blockDim.x + threadIdx.x) >> 5;
    int lane = threadIdx.x & 31;
    if (warp >= NN) return;
    int i = warp;
    float di = g_dis[i];
    float ws = di * di;
    float acc[CH];
#pragma unroll
    for (int cc = 0; cc < CH; cc++)
        acc[cc] = h[(size_t)i * DOUT + cc * 32 + lane] * ws;
    int e = g_offs[i];
    int end = e + g_cnt[i];
    // 2-way unroll for MLP
    for (; e + 1 < end; e += 2) {
        int j0 = g_csrc[e], j1 = g_csrc[e + 1];
        float w0 = g_dis[j0] * di, w1 = g_dis[j1] * di;
        const float* p0 = h + (size_t)j0 * DOUT + lane;
        const float* p1 = h + (size_t)j1 * DOUT + lane;
#pragma unroll
        for (int cc = 0; cc < CH; cc++)
            acc[cc] += p0[cc * 32] * w0 + p1[cc * 32] * w1;
    }
    if (e < end) {
        int j = g_csrc[e];
        float w = g_dis[j] * di;
        const float* p = h + (size_t)j * DOUT + lane;
#pragma unroll
        for (int cc = 0; cc < CH; cc++)
            acc[cc] += p[cc * 32] * w;
    }
#pragma unroll
    for (int cc = 0; cc < CH; cc++)
        y[(size_t)i * DOUT + cc * 32 + lane] = acc[cc] + bias[cc * 32 + lane];
}

// ---------------- BatchNorm ------------------------------------------------
__global__ void bn_reduce(const float* __restrict__ x, int dout, int layer) {
    int col = threadIdx.x;  // blockDim.x == dout
    float s = 0.f, q = 0.f;
    for (int r = blockIdx.x; r < NN; r += gridDim.x) {
        float v = x[(size_t)r * dout + col];
        s += v;
        q += v * v;
    }
    atomicAdd(&g_bnsum[layer][col], s);
    atomicAdd(&g_bnsq[layer][col], q);
}

__global__ void bn_finalize(const float* __restrict__ g, const float* __restrict__ b,
                            int dout, int layer) {
    int c = threadIdx.x;
    if (c >= dout) return;
    float mean = g_bnsum[layer][c] * (1.f / NN);
    float var = g_bnsq[layer][c] * (1.f / NN) - mean * mean;
    float istd = rsqrtf(var + 1e-5f);
    float sc = g[c] * istd;
    g_bnscale[c] = sc;
    g_bnshift[c] = b[c] - mean * sc;
}

__global__ void bn_apply(float* __restrict__ x, int dout, int leaky) {
    size_t total = (size_t)NN * dout;
    size_t i = (size_t)blockIdx.x * blockDim.x + threadIdx.x;
    size_t stride = (size_t)gridDim.x * blockDim.x;
    int mask = dout - 1;
    for (size_t t = i; t < total; t += stride) {
        int col = (int)(t & mask);
        float v = x[t] * g_bnscale[col] + g_bnshift[col];
        if (leaky) v = lrelu(v);
        x[t] = v;
    }
}

// ---------------- GAT ------------------------------------------------------
template <int DOUT>
__global__ void attn_coef(const float* __restrict__ hg, const float* __restrict__ av_src,
                          const float* __restrict__ av_dst) {
    constexpr int CH = DOUT / 32;
    constexpr int C = DOUT / 4;
    int warp = (blockIdx.x * blockDim.x + threadIdx.x) >> 5;
    int lane = threadIdx.x & 31;
    if (warp >= NN) return;
    int i = warp;
#pragma unroll
    for (int cc = 0; cc < CH; cc++) {
        int col = cc * 32 + lane;
        float hv = hg[(size_t)i * DOUT + col];
        float v1 = hv * av_src[col];
        float v2 = hv * av_dst[col];
#pragma unroll
        for (int off = C / 2 >= 16 ? 16 : C / 2; off > 0; off >>= 1) {
            v1 += __shfl_down_sync(0xffffffffu, v1, off);
            v2 += __shfl_down_sync(0xffffffffu, v2, off);
        }
        if ((lane % C) == 0) {
            int hh = col / C;
            g_an_src[i * 4 + hh] = v1;
            g_an_dst[i * 4 + hh] = v2;
        }
    }
}

template <int DOUT>
__global__ void gat_agg(const float* __restrict__ hg, const float* __restrict__ yres,
                        const float* __restrict__ bias, float* __restrict__ xout) {
    constexpr int CH = DOUT / 32;
    constexpr int C = DOUT / 4;
    int warp = (blockIdx.x * blockDim.x + threadIdx.x) >> 5;
    int lane = threadIdx.x & 31;
    if (warp >= NN) return;
    int i = warp;
    float4 asi = *(const float4*)&g_an_src[i * 4];
    float4 adi = *(const float4*)&g_an_dst[i * 4];
    float e0 = lrelu(asi.x + adi.x);
    float e1 = lrelu(asi.y + adi.y);
    float e2 = lrelu(asi.z + adi.z);
    float e3 = lrelu(asi.w + adi.w);
    float m0 = e0, m1 = e1, m2 = e2, m3 = e3;
    int s = g_offs[i], cnt = g_cnt[i];
    // pass 1: max over incoming edge logits (lanes strided over edges)
    for (int e = s + lane; e < s + cnt; e += 32) {
        int j = g_csrc[e];
        float4 aj = *(const float4*)&g_an_src[j * 4];
        m0 = fmaxf(m0, lrelu(aj.x + adi.x));
        m1 = fmaxf(m1, lrelu(aj.y + adi.y));
        m2 = fmaxf(m2, lrelu(aj.z + adi.z));
        m3 = fmaxf(m3, lrelu(aj.w + adi.w));
    }
#pragma unroll
    for (int off = 16; off > 0; off >>= 1) {
        m0 = fmaxf(m0, __shfl_xor_sync(0xffffffffu, m0, off));
        m1 = fmaxf(m1, __shfl_xor_sync(0xffffffffu, m1, off));
        m2 = fmaxf(m2, __shfl_xor_sync(0xffffffffu, m2, off));
        m3 = fmaxf(m3, __shfl_xor_sync(0xffffffffu, m3, off));
    }
    // self edge
    float p0 = __expf(e0 - m0), p1 = __expf(e1 - m1);
    float p2 = __expf(e2 - m2), p3 = __expf(e3 - m3);
    float den0 = p0, den1 = p1, den2 = p2, den3 = p3;
    int hh[CH];
    float acc[CH];
#pragma unroll
    for (int cc = 0; cc < CH; cc++) {
        hh[cc] = (cc * 32 + lane) / C;
        float p = hh[cc] == 0 ? p0 : hh[cc] == 1 ? p1 : hh[cc] == 2 ? p2 : p3;
        acc[cc] = hg[(size_t)i * DOUT + cc * 32 + lane] * p;
    }
    // pass 2: weighted gather, 2-way unrolled
    int e = s, end = s + cnt;
    for (; e + 1 < end; e += 2) {
        int j0 = g_csrc[e], j1 = g_csrc[e + 1];
        float4 a0 = *(const float4*)&g_an_src[j0 * 4];
        float4 a1 = *(const float4*)&g_an_src[j1 * 4];
        float q00 = __expf(lrelu(a0.x + adi.x) - m0);
        float q01 = __expf(lrelu(a0.y + adi.y) - m1);
        float q02 = __expf(lrelu(a0.z + adi.z) - m2);
        float q03 = __expf(lrelu(a0.w + adi.w) - m3);
        float q10 = __expf(lrelu(a1.x + adi.x) - m0);
        float q11 = __expf(lrelu(a1.y + adi.y) - m1);
        float q12 = __expf(lrelu(a1.z + adi.z) - m2);
        float q13 = __expf(lrelu(a1.w + adi.w) - m3);
        den0 += q00 + q10; den1 += q01 + q11;
        den2 += q02 + q12; den3 += q03 + q13;
        const float* p0 = hg + (size_t)j0 * DOUT + lane;
        const float* p1 = hg + (size_t)j1 * DOUT + lane;
#pragma unroll
        for (int cc = 0; cc < CH; cc++) {
            float qa = hh[cc] == 0 ? q00 : hh[cc] == 1 ? q01 : hh[cc] == 2 ? q02 : q03;
            float qb = hh[cc] == 0 ? q10 : hh[cc] == 1 ? q11 : hh[cc] == 2 ? q12 : q13;
            acc[cc] += p0[cc * 32] * qa + p1[cc * 32] * qb;
        }
    }
    if (e < end) {
        int j = g_csrc[e];
        float4 aj = *(const float4*)&g_an_src[j * 4];
        float q0 = __expf(lrelu(aj.x + adi.x) - m0);
        float q1 = __expf(lrelu(aj.y + adi.y) - m1);
        float q2 = __expf(lrelu(aj.z + adi.z) - m2);
        float q3 = __expf(lrelu(aj.w + adi.w) - m3);
        den0 += q0; den1 += q1; den2 += q2; den3 += q3;
        const float* p = hg + (size_t)j * DOUT + lane;
#pragma unroll
        for (int cc = 0; cc < CH; cc++) {
            float q = hh[cc] == 0 ? q0 : hh[cc] == 1 ? q1 : hh[cc] == 2 ? q2 : q3;
            acc[cc] += p[cc * 32] * q;
        }
    }
#pragma unroll
    for (int cc = 0; cc < CH; cc++) {
        float d = hh[cc] == 0 ? den0 : hh[cc] == 1 ? den1 : hh[cc] == 2 ? den2 : den3;
        int col = cc * 32 + lane;
        float v = acc[cc] / d + bias[col] + yres[(size_t)i * DOUT + col];
        xout[(size_t)i * DOUT + col] = lrelu(v);
    }
}

// ---------------- pooling --------------------------------------------------
__global__ void pool_acc(const float* __restrict__ x, const int* __restrict__ batch) {
    size_t total = (size_t)NN * 64;
    size_t i = (size_t)blockIdx.x * blockDim.x + threadIdx.x;
    size_t stride = (size_t)gridDim.x * blockDim.x;
    for (size_t t = i; t < total; t += stride) {
        int node = (int)(t >> 6);
        int c = (int)(t & 63);
        atomicAdd(&g_pool[batch[node] * 64 + c], x[t]);
    }
}

__global__ void pool_fin(float* __restrict__ out) {
    int i = blockIdx.x * blockDim.x + threadIdx.x;
    if (i < GG * 64) {
        int g = i >> 6;
        out[i] = g_pool[i] / fmaxf(g_pcnt[g], 1.f);
    }
}

// ---------------- host orchestration --------------------------------------
extern "C" void kernel_launch(void* const* d_in, const int* in_sizes, int n_in,
                              void* d_out, int out_size) {
    const float* x_in = (const float*)d_in[0];
    const int* ei = (const int*)d_in[1];
    const int* batch = (const int*)d_in[2];

    const float* gcn_w[4] = {(const float*)d_in[3], (const float*)d_in[7],
                             (const float*)d_in[11], (const float*)d_in[15]};
    const float* gcn_b[4] = {(const float*)d_in[4], (const float*)d_in[8],
                             (const float*)d_in[12], (const float*)d_in[16]};
    const float* bn_g[4] = {(const float*)d_in[5], (const float*)d_in[9],
                            (const float*)d_in[13], (const float*)d_in[17]};
    const float* bn_b[4] = {(const float*)d_in[6], (const float*)d_in[10],
                            (const float*)d_in[14], (const float*)d_in[18]};
    const float* gat_w[2] = {(const float*)d_in[19], (const float*)d_in[23]};
    const float* gat_as[2] = {(const float*)d_in[20], (const float*)d_in[24]};
    const float* gat_ad[2] = {(const float*)d_in[21], (const float*)d_in[25]};
    const float* gat_b[2] = {(const float*)d_in[22], (const float*)d_in[26]};

    float *px, *py, *ph, *phg;
    cudaGetSymbolAddress((void**)&px, g_x);
    cudaGetSymbolAddress((void**)&py, g_y);
    cudaGetSymbolAddress((void**)&ph, g_h);
    cudaGetSymbolAddress((void**)&phg, g_hg);

    const int warp_blocks = (NN * 32 + 255) / 256;
    const int dims[5] = {16, 64, 128, 128, 64};

    // CSR build (layer0 GEMM placed 4th so ncu -s5 captures it)
    zero_init<<<256, 256>>>();
    hist_k<<<1024, 256>>>(ei + EE, batch);
    scan1<<<NB_SCAN, 1024>>>();
    {
        dim3 gg((NN + 63) / 64, dims[1] / 64);
        gemm_tf32<<<gg, 256>>>(x_in, gcn_w[0], ph, NN, 16, dims[1]);
    }
    scan2<<<1, 128>>>();
    scan3_dis<<<NB_SCAN, 1024>>>();
    scatter_k<<<1024, 256>>>(ei, ei + EE);

    const float* cur = x_in;
    int din = 16;
    for (int i = 0; i < 4; i++) {
        int dout = dims[i + 1];
        if (i > 0) {  // layer0 GEMM already issued above
            dim3 gg((NN + 63) / 64, dout / 64);
            gemm_tf32<<<gg, 256>>>(cur, gcn_w[i], ph, NN, din, dout);
        }
        if (dout == 64) gcn_agg<64><<<warp_blocks, 256>>>(ph, gcn_b[i], py);
        else            gcn_agg<128><<<warp_blocks, 256>>>(ph, gcn_b[i], py);
        bn_reduce<<<240, dout>>>(py, dout, i);
        bn_finalize<<<1, 128>>>(bn_g[i], bn_b[i], dout, i);
        bn_apply<<<1024, 256>>>(py, dout, (i == 1) ? 1 : 0);
        if (i == 0 || i == 2) {
            int gi = (i == 0) ? 0 : 1;
            dim3 gg2((NN + 63) / 64, dout / 64);
            gemm_tf32<<<gg2, 256>>>(py, gat_w[gi], phg, NN, dout, dout);
            if (dout == 64) {
                attn_coef<64><<<warp_blocks, 256>>>(phg, gat_as[gi], gat_ad[gi]);
                gat_agg<64><<<warp_blocks, 256>>>(phg, py, gat_b[gi], px);
            } else {
                attn_coef<128><<<warp_blocks, 256>>>(phg, gat_as[gi], gat_ad[gi]);
                gat_agg<128><<<warp_blocks, 256>>>(phg, py, gat_b[gi], px);
            }
            cur = px;
        } else {
            cur = py;
        }
        din = dout;
    }

    pool_acc<<<1024, 256>>>(cur, batch);
    pool_fin<<<(GG * 64 + 255) / 256, 256>>>((float*)d_out);
}

// round 3
// speedup vs baseline: 1.6689x; 1.3762x over previous
#include <cuda_runtime.h>
#include <math.h>
#include <mma.h>

using namespace nvcuda;

#define NN 100000
#define NPAD 100032            /* 1563 * 64 */
#define EE 1600000
#define GG 256
#define NB_SCAN 98             /* ceil(NN/1024) */

// ---------------- scratch (device globals; no allocation allowed) ----------
__device__ float g_x[NPAD * 128];
__device__ float g_y[NPAD * 128];
__device__ float g_h[NPAD * 128];
__device__ float g_hg[NPAD * 128];
__device__ int   g_cnt[NN];
__device__ int   g_offs[NN];
__device__ int   g_cursor[NN];
__device__ int   g_csrc[EE];
__device__ float g_dis[NN];
__device__ float g_an_src[NN * 4];
__device__ float g_an_dst[NN * 4];
__device__ float g_bnsum[4][128];
__device__ float g_bnsq[4][128];
__device__ float g_bnscale[4][128];
__device__ float g_bnshift[4][128];
__device__ int   g_bsum[128];
__device__ float g_pool[GG * 64];
__device__ float g_pcnt[GG];

__device__ __forceinline__ float lrelu(float v) { return v > 0.f ? v : 0.2f * v; }

// ---------------- init / CSR build ----------------------------------------
__global__ void zero_init() {
    int i = blockIdx.x * blockDim.x + threadIdx.x;
    int stride = gridDim.x * blockDim.x;
    for (int t = i; t < NN; t += stride) { g_cnt[t] = 0; g_cursor[t] = 0; }
    for (int t = i; t < GG * 64; t += stride) g_pool[t] = 0.f;
    for (int t = i; t < GG; t += stride) g_pcnt[t] = 0.f;
    for (int t = i; t < 4 * 128; t += stride) { (&g_bnsum[0][0])[t] = 0.f; (&g_bnsq[0][0])[t] = 0.f; }
}

__global__ void hist_k(const int* __restrict__ col, const int* __restrict__ batch) {
    int i = blockIdx.x * blockDim.x + threadIdx.x;
    int stride = gridDim.x * blockDim.x;
    for (int e = i; e < EE; e += stride)
        atomicAdd(&g_cnt[col[e]], 1);
    for (int t = i; t < NN; t += stride)
        atomicAdd(&g_pcnt[batch[t]], 1.f);
}

__global__ void scan1() {
    __shared__ int s[1024];
    int t = threadIdx.x;
    int gi = blockIdx.x * 1024 + t;
    int v = (gi < NN) ? g_cnt[gi] : 0;
    s[t] = v;
    for (int off = 1; off < 1024; off <<= 1) {
        __syncthreads();
        int u = (t >= off) ? s[t - off] : 0;
        __syncthreads();
        s[t] += u;
    }
    if (gi < NN) g_offs[gi] = s[t] - v;   // exclusive within chunk
    if (t == 1023) g_bsum[blockIdx.x] = s[1023];
}

__global__ void scan2() {
    int t = threadIdx.x;
    int lane = t & 31, w = t >> 5;
    int v = (t < NB_SCAN) ? g_bsum[t] : 0;
    int x = v;
#pragma unroll
    for (int off = 1; off < 32; off <<= 1) {
        int u = __shfl_up_sync(0xffffffffu, x, off);
        if (lane >= off) x += u;
    }
    __shared__ int wsum[4];
    if (lane == 31) wsum[w] = x;
    __syncthreads();
    int add = 0;
    for (int i = 0; i < w; i++) add += wsum[i];
    x += add;
    if (t < NB_SCAN) g_bsum[t] = x - v;   // exclusive
}

__global__ void scan3_dis() {
    int gi = blockIdx.x * 1024 + threadIdx.x;
    if (gi < NN) {
        g_offs[gi] += g_bsum[blockIdx.x];
        g_dis[gi] = rsqrtf((float)(g_cnt[gi] + 1));  // +1 self loop
    }
}

__global__ void scatter_k(const int* __restrict__ row, const int* __restrict__ col) {
    int i = blockIdx.x * blockDim.x + threadIdx.x;
    for (int e = i; e < EE; e += gridDim.x * blockDim.x) {
        int c = col[e];
        int pos = g_offs[c] + atomicAdd(&g_cursor[c], 1);
        g_csrc[pos] = row[e];
    }
}

// ---------------- GEMM: 3xTF32 WMMA with pre-split smem tiles --------------
// TRANS: 0 = none, 1 = A'=A*sc+sh, 2 = A'=lrelu(A*sc+sh)
#define BM 64
#define BN 64
#define BK 32

template <int TRANS>
__global__ void gemm_tf32(const float* __restrict__ A, const float* __restrict__ W,
                          float* __restrict__ out, int n, int din, int dout,
                          const float* __restrict__ sc, const float* __restrict__ sh) {
    __shared__ float As[2][BM][BK + 8];   // hi / lo
    __shared__ float Bs[2][BK][BN + 8];
    int tid = threadIdx.x;
    int warp = tid >> 5;
    int wr = warp >> 1;
    int wc = warp & 1;
    int row0 = blockIdx.x * BM;
    int col0 = blockIdx.y * BN;

    wmma::fragment<wmma::accumulator, 16, 16, 8, float> acc[2];
    wmma::fill_fragment(acc[0], 0.f);
    wmma::fill_fragment(acc[1], 0.f);

    for (int k0 = 0; k0 < din; k0 += BK) {
#pragma unroll
        for (int v = tid; v < BM * 8; v += 256) {
            int r = v >> 3;
            int kk = (v & 7) * 4;
            float4 val = make_float4(0.f, 0.f, 0.f, 0.f);
            int grow = row0 + r, gk = k0 + kk;
            if (grow < n && gk < din) {
                val = *(const float4*)(A + (size_t)grow * din + gk);
                if (TRANS > 0) {
                    float4 s4 = *(const float4*)(sc + gk);
                    float4 h4 = *(const float4*)(sh + gk);
                    val.x = val.x * s4.x + h4.x;
                    val.y = val.y * s4.y + h4.y;
                    val.z = val.z * s4.z + h4.z;
                    val.w = val.w * s4.w + h4.w;
                    if (TRANS == 2) {
                        val.x = lrelu(val.x); val.y = lrelu(val.y);
                        val.z = lrelu(val.z); val.w = lrelu(val.w);
                    }
                }
            }
            float4 hi, lo;
            hi.x = wmma::__float_to_tf32(val.x); lo.x = wmma::__float_to_tf32(val.x - hi.x);
            hi.y = wmma::__float_to_tf32(val.y); lo.y = wmma::__float_to_tf32(val.y - hi.y);
            hi.z = wmma::__float_to_tf32(val.z); lo.z = wmma::__float_to_tf32(val.z - hi.z);
            hi.w = wmma::__float_to_tf32(val.w); lo.w = wmma::__float_to_tf32(val.w - hi.w);
            *(float4*)&As[0][r][kk] = hi;
            *(float4*)&As[1][r][kk] = lo;
        }
#pragma unroll
        for (int v = tid; v < BK * 16; v += 256) {
            int kk = v >> 4;
            int cc = (v & 15) * 4;
            float4 val = make_float4(0.f, 0.f, 0.f, 0.f);
            int gk = k0 + kk;
            if (gk < din)
                val = *(const float4*)(W + (size_t)gk * dout + col0 + cc);
            float4 hi, lo;
            hi.x = wmma::__float_to_tf32(val.x); lo.x = wmma::__float_to_tf32(val.x - hi.x);
            hi.y = wmma::__float_to_tf32(val.y); lo.y = wmma::__float_to_tf32(val.y - hi.y);
            hi.z = wmma::__float_to_tf32(val.z); lo.z = wmma::__float_to_tf32(val.z - hi.z);
            hi.w = wmma::__float_to_tf32(val.w); lo.w = wmma::__float_to_tf32(val.w - hi.w);
            *(float4*)&Bs[0][kk][cc] = hi;
            *(float4*)&Bs[1][kk][cc] = lo;
        }
        __syncthreads();

#pragma unroll
        for (int ks = 0; ks < BK; ks += 8) {
            wmma::fragment<wmma::matrix_a, 16, 16, 8, wmma::precision::tf32, wmma::row_major> a_hi, a_lo;
            wmma::load_matrix_sync(a_hi, &As[0][wr * 16][ks], BK + 8);
            wmma::load_matrix_sync(a_lo, &As[1][wr * 16][ks], BK + 8);
#pragma unroll
            for (int c = 0; c < 2; c++) {
                wmma::fragment<wmma::matrix_b, 16, 16, 8, wmma::precision::tf32, wmma::row_major> b_hi, b_lo;
                wmma::load_matrix_sync(b_hi, &Bs[0][ks][wc * 32 + c * 16], BN + 8);
                wmma::load_matrix_sync(b_lo, &Bs[1][ks][wc * 32 + c * 16], BN + 8);
                wmma::mma_sync(acc[c], a_hi, b_hi, acc[c]);
                wmma::mma_sync(acc[c], a_lo, b_hi, acc[c]);
                wmma::mma_sync(acc[c], a_hi, b_lo, acc[c]);
            }
        }
        __syncthreads();
    }
    int grow = row0 + wr * 16;   // out is NPAD-padded scratch: unguarded store
#pragma unroll
    for (int c = 0; c < 2; c++)
        wmma::store_matrix_sync(out + (size_t)grow * dout + col0 + wc * 32 + c * 16,
                                acc[c], dout, wmma::mem_row_major);
}

// ---------------- GCN aggregation + fused BN statistics --------------------
template <int DOUT>
__global__ void gcn_agg(const float* __restrict__ h, const float* __restrict__ bias,
                        float* __restrict__ y, int layer) {
    constexpr int CH = DOUT / 32;
    __shared__ float sS[DOUT], sQ[DOUT];
    int tid = threadIdx.x;
    for (int t = tid; t < DOUT; t += blockDim.x) { sS[t] = 0.f; sQ[t] = 0.f; }
    __syncthreads();
    int lane = tid & 31;
    int gw = (blockIdx.x * blockDim.x + tid) >> 5;
    int nw = (gridDim.x * blockDim.x) >> 5;
    float bs[CH];
#pragma unroll
    for (int cc = 0; cc < CH; cc++) bs[cc] = bias[cc * 32 + lane];
    float stS[CH], stQ[CH];
#pragma unroll
    for (int cc = 0; cc < CH; cc++) { stS[cc] = 0.f; stQ[cc] = 0.f; }

    for (int i = gw; i < NN; i += nw) {
        float di = g_dis[i];
        float ws = di * di;
        float acc[CH];
#pragma unroll
        for (int cc = 0; cc < CH; cc++)
            acc[cc] = h[(size_t)i * DOUT + cc * 32 + lane] * ws;
        int e = g_offs[i];
        int end = e + g_cnt[i];
        for (; e + 1 < end; e += 2) {
            int j0 = g_csrc[e], j1 = g_csrc[e + 1];
            float w0 = g_dis[j0] * di, w1 = g_dis[j1] * di;
            const float* p0 = h + (size_t)j0 * DOUT + lane;
            const float* p1 = h + (size_t)j1 * DOUT + lane;
#pragma unroll
            for (int cc = 0; cc < CH; cc++)
                acc[cc] += p0[cc * 32] * w0 + p1[cc * 32] * w1;
        }
        if (e < end) {
            int j = g_csrc[e];
            float w = g_dis[j] * di;
            const float* p = h + (size_t)j * DOUT + lane;
#pragma unroll
            for (int cc = 0; cc < CH; cc++)
                acc[cc] += p[cc * 32] * w;
        }
#pragma unroll
        for (int cc = 0; cc < CH; cc++) {
            float v = acc[cc] + bs[cc];
            y[(size_t)i * DOUT + cc * 32 + lane] = v;
            stS[cc] += v;
            stQ[cc] += v * v;
        }
    }
#pragma unroll
    for (int cc = 0; cc < CH; cc++) {
        atomicAdd(&sS[cc * 32 + lane], stS[cc]);
        atomicAdd(&sQ[cc * 32 + lane], stQ[cc]);
    }
    __syncthreads();
    for (int t = tid; t < DOUT; t += blockDim.x) {
        atomicAdd(&g_bnsum[layer][t], sS[t]);
        atomicAdd(&g_bnsq[layer][t], sQ[t]);
    }
}

// ---------------- BatchNorm: finalize affine table only --------------------
__global__ void bn_finalize(const float* __restrict__ g, const float* __restrict__ b,
                            int dout, int layer) {
    int c = threadIdx.x;
    if (c >= dout) return;
    float mean = g_bnsum[layer][c] * (1.f / NN);
    float var = g_bnsq[layer][c] * (1.f / NN) - mean * mean;
    float istd = rsqrtf(var + 1e-5f);
    float scv = g[c] * istd;
    g_bnscale[layer][c] = scv;
    g_bnshift[layer][c] = b[c] - mean * scv;
}

// ---------------- GAT ------------------------------------------------------
template <int DOUT>
__global__ void attn_coef(const float* __restrict__ hg, const float* __restrict__ av_src,
                          const float* __restrict__ av_dst) {
    constexpr int CH = DOUT / 32;
    constexpr int C = DOUT / 4;
    int warp = (blockIdx.x * blockDim.x + threadIdx.x) >> 5;
    int lane = threadIdx.x & 31;
    if (warp >= NN) return;
    int i = warp;
#pragma unroll
    for (int cc = 0; cc < CH; cc++) {
        int col = cc * 32 + lane;
        float hv = hg[(size_t)i * DOUT + col];
        float v1 = hv * av_src[col];
        float v2 = hv * av_dst[col];
#pragma unroll
        for (int off = C / 2 >= 16 ? 16 : C / 2; off > 0; off >>= 1) {
            v1 += __shfl_down_sync(0xffffffffu, v1, off);
            v2 += __shfl_down_sync(0xffffffffu, v2, off);
        }
        if ((lane % C) == 0) {
            int hh = col / C;
            g_an_src[i * 4 + hh] = v1;
            g_an_dst[i * 4 + hh] = v2;
        }
    }
}

template <int DOUT>
__global__ void gat_agg(const float* __restrict__ hg, const float* __restrict__ yres,
                        const float* __restrict__ bias, float* __restrict__ xout,
                        const float* __restrict__ rsc, const float* __restrict__ rsh) {
    constexpr int CH = DOUT / 32;
    constexpr int C = DOUT / 4;
    int warp = (blockIdx.x * blockDim.x + threadIdx.x) >> 5;
    int lane = threadIdx.x & 31;
    if (warp >= NN) return;
    int i = warp;
    float4 asi = *(const float4*)&g_an_src[i * 4];
    float4 adi = *(const float4*)&g_an_dst[i * 4];
    float e0 = lrelu(asi.x + adi.x);
    float e1 = lrelu(asi.y + adi.y);
    float e2 = lrelu(asi.z + adi.z);
    float e3 = lrelu(asi.w + adi.w);
    float m0 = e0, m1 = e1, m2 = e2, m3 = e3;
    int s = g_offs[i], cnt = g_cnt[i];
    for (int e = s + lane; e < s + cnt; e += 32) {
        int j = g_csrc[e];
        float4 aj = *(const float4*)&g_an_src[j * 4];
        m0 = fmaxf(m0, lrelu(aj.x + adi.x));
        m1 = fmaxf(m1, lrelu(aj.y + adi.y));
        m2 = fmaxf(m2, lrelu(aj.z + adi.z));
        m3 = fmaxf(m3, lrelu(aj.w + adi.w));
    }
#pragma unroll
    for (int off = 16; off > 0; off >>= 1) {
        m0 = fmaxf(m0, __shfl_xor_sync(0xffffffffu, m0, off));
        m1 = fmaxf(m1, __shfl_xor_sync(0xffffffffu, m1, off));
        m2 = fmaxf(m2, __shfl_xor_sync(0xffffffffu, m2, off));
        m3 = fmaxf(m3, __shfl_xor_sync(0xffffffffu, m3, off));
    }
    float p0 = __expf(e0 - m0), p1 = __expf(e1 - m1);
    float p2 = __expf(e2 - m2), p3 = __expf(e3 - m3);
    float den0 = p0, den1 = p1, den2 = p2, den3 = p3;
    int hh[CH];
    float acc[CH];
#pragma unroll
    for (int cc = 0; cc < CH; cc++) {
        hh[cc] = (cc * 32 + lane) / C;
        float p = hh[cc] == 0 ? p0 : hh[cc] == 1 ? p1 : hh[cc] == 2 ? p2 : p3;
        acc[cc] = hg[(size_t)i * DOUT + cc * 32 + lane] * p;
    }
    int e = s, end = s + cnt;
    for (; e + 1 < end; e += 2) {
        int j0 = g_csrc[e], j1 = g_csrc[e + 1];
        float4 a0 = *(const float4*)&g_an_src[j0 * 4];
        float4 a1 = *(const float4*)&g_an_src[j1 * 4];
        float q00 = __expf(lrelu(a0.x + adi.x) - m0);
        float q01 = __expf(lrelu(a0.y + adi.y) - m1);
        float q02 = __expf(lrelu(a0.z + adi.z) - m2);
        float q03 = __expf(lrelu(a0.w + adi.w) - m3);
        float q10 = __expf(lrelu(a1.x + adi.x) - m0);
        float q11 = __expf(lrelu(a1.y + adi.y) - m1);
        float q12 = __expf(lrelu(a1.z + adi.z) - m2);
        float q13 = __expf(lrelu(a1.w + adi.w) - m3);
        den0 += q00 + q10; den1 += q01 + q11;
        den2 += q02 + q12; den3 += q03 + q13;
        const float* p0 = hg + (size_t)j0 * DOUT + lane;
        const float* p1 = hg + (size_t)j1 * DOUT + lane;
#pragma unroll
        for (int cc = 0; cc < CH; cc++) {
            float qa = hh[cc] == 0 ? q00 : hh[cc] == 1 ? q01 : hh[cc] == 2 ? q02 : q03;
            float qb = hh[cc] == 0 ? q10 : hh[cc] == 1 ? q11 : hh[cc] == 2 ? q12 : q13;
            acc[cc] += p0[cc * 32] * qa + p1[cc * 32] * qb;
        }
    }
    if (e < end) {
        int j = g_csrc[e];
        float4 aj = *(const float4*)&g_an_src[j * 4];
        float q0 = __expf(lrelu(aj.x + adi.x) - m0);
        float q1 = __expf(lrelu(aj.y + adi.y) - m1);
        float q2 = __expf(lrelu(aj.z + adi.z) - m2);
        float q3 = __expf(lrelu(aj.w + adi.w) - m3);
        den0 += q0; den1 += q1; den2 += q2; den3 += q3;
        const float* p = hg + (size_t)j * DOUT + lane;
#pragma unroll
        for (int cc = 0; cc < CH; cc++) {
            float q = hh[cc] == 0 ? q0 : hh[cc] == 1 ? q1 : hh[cc] == 2 ? q2 : q3;
            acc[cc] += p[cc * 32] * q;
        }
    }
#pragma unroll
    for (int cc = 0; cc < CH; cc++) {
        float d = hh[cc] == 0 ? den0 : hh[cc] == 1 ? den1 : hh[cc] == 2 ? den2 : den3;
        int col = cc * 32 + lane;
        float res = yres[(size_t)i * DOUT + col] * rsc[col] + rsh[col];  // BN fused
        float v = acc[cc] / d + bias[col] + res;
        xout[(size_t)i * DOUT + col] = lrelu(v);
    }
}

// ---------------- pooling (BN fused on read) -------------------------------
__global__ void pool_acc(const float* __restrict__ x, const int* __restrict__ batch,
                         const float* __restrict__ sc, const float* __restrict__ sh) {
    size_t total = (size_t)NN * 64;
    size_t i = (size_t)blockIdx.x * blockDim.x + threadIdx.x;
    size_t stride = (size_t)gridDim.x * blockDim.x;
    for (size_t t = i; t < total; t += stride) {
        int node = (int)(t >> 6);
        int c = (int)(t & 63);
        float v = x[t] * sc[c] + sh[c];
        atomicAdd(&g_pool[batch[node] * 64 + c], v);
    }
}

__global__ void pool_fin(float* __restrict__ out) {
    int i = blockIdx.x * blockDim.x + threadIdx.x;
    if (i < GG * 64) {
        int g = i >> 6;
        out[i] = g_pool[i] / fmaxf(g_pcnt[g], 1.f);
    }
}

// ---------------- host orchestration --------------------------------------
extern "C" void kernel_launch(void* const* d_in, const int* in_sizes, int n_in,
                              void* d_out, int out_size) {
    const float* x_in = (const float*)d_in[0];
    const int* ei = (const int*)d_in[1];
    const int* batch = (const int*)d_in[2];

    const float* gcn_w[4] = {(const float*)d_in[3], (const float*)d_in[7],
                             (const float*)d_in[11], (const float*)d_in[15]};
    const float* gcn_b[4] = {(const float*)d_in[4], (const float*)d_in[8],
                             (const float*)d_in[12], (const float*)d_in[16]};
    const float* bn_g[4] = {(const float*)d_in[5], (const float*)d_in[9],
                            (const float*)d_in[13], (const float*)d_in[17]};
    const float* bn_b[4] = {(const float*)d_in[6], (const float*)d_in[10],
                            (const float*)d_in[14], (const float*)d_in[18]};
    const float* gat_w[2] = {(const float*)d_in[19], (const float*)d_in[23]};
    const float* gat_as[2] = {(const float*)d_in[20], (const float*)d_in[24]};
    const float* gat_ad[2] = {(const float*)d_in[21], (const float*)d_in[25]};
    const float* gat_b[2] = {(const float*)d_in[22], (const float*)d_in[26]};

    float *px, *py, *ph, *phg, *psc, *psh;
    cudaGetSymbolAddress((void**)&px, g_x);
    cudaGetSymbolAddress((void**)&py, g_y);
    cudaGetSymbolAddress((void**)&ph, g_h);
    cudaGetSymbolAddress((void**)&phg, g_hg);
    cudaGetSymbolAddress((void**)&psc, g_bnscale);
    cudaGetSymbolAddress((void**)&psh, g_bnshift);
    const float* sc[4] = {psc, psc + 128, psc + 256, psc + 384};
    const float* sh[4] = {psh, psh + 128, psh + 256, psh + 384};

    const int warp_blocks = (NN * 32 + 255) / 256;  // 1 warp per node kernels
    const int agg_blocks = 148 * 8;                 // grid-stride gcn_agg

    // ---- CSR build (+ layer0 GEMM interleaved; profiled launch = #4) ----
    zero_init<<<256, 256>>>();
    hist_k<<<1024, 256>>>(ei + EE, batch);
    scan1<<<NB_SCAN, 1024>>>();
    {
        dim3 gg((NN + 63) / 64, 1);
        gemm_tf32<0><<<gg, 256>>>(x_in, gcn_w[0], ph, NN, 16, 64, nullptr, nullptr);
    }
    scan2<<<1, 128>>>();
    scan3_dis<<<NB_SCAN, 1024>>>();
    scatter_k<<<1024, 256>>>(ei, ei + EE);

    // ---- layer 0 (16 -> 64, GAT) ----
    gcn_agg<64><<<agg_blocks, 256>>>(ph, gcn_b[0], py, 0);
    bn_finalize<<<1, 128>>>(bn_g[0], bn_b[0], 64, 0);
    {
        dim3 gg((NN + 63) / 64, 1);
        gemm_tf32<1><<<gg, 256>>>(py, gat_w[0], phg, NN, 64, 64, sc[0], sh[0]);
    }
    attn_coef<64><<<warp_blocks, 256>>>(phg, gat_as[0], gat_ad[0]);
    gat_agg<64><<<warp_blocks, 256>>>(phg, py, gat_b[0], px, sc[0], sh[0]);

    // ---- layer 1 (64 -> 128, no GAT, leaky into next gemm) ----
    {
        dim3 gg((NN + 63) / 64, 2);
        gemm_tf32<0><<<gg, 256>>>(px, gcn_w[1], ph, NN, 64, 128, nullptr, nullptr);
    }
    gcn_agg<128><<<agg_blocks, 256>>>(ph, gcn_b[1], py, 1);
    bn_finalize<<<1, 128>>>(bn_g[1], bn_b[1], 128, 1);

    // ---- layer 2 (128 -> 128, GAT); BN1+leaky fused into A load ----
    {
        dim3 gg((NN + 63) / 64, 2);
        gemm_tf32<2><<<gg, 256>>>(py, gcn_w[2], ph, NN, 128, 128, sc[1], sh[1]);
    }
    gcn_agg<128><<<agg_blocks, 256>>>(ph, gcn_b[2], py, 2);
    bn_finalize<<<1, 128>>>(bn_g[2], bn_b[2], 128, 2);
    {
        dim3 gg((NN + 63) / 64, 2);
        gemm_tf32<1><<<gg, 256>>>(py, gat_w[1], phg, NN, 128, 128, sc[2], sh[2]);
    }
    attn_coef<128><<<warp_blocks, 256>>>(phg, gat_as[1], gat_ad[1]);
    gat_agg<128><<<warp_blocks, 256>>>(phg, py, gat_b[1], px, sc[2], sh[2]);

    // ---- layer 3 (128 -> 64, no GAT, no trailing leaky) ----
    {
        dim3 gg((NN + 63) / 64, 1);
        gemm_tf32<0><<<gg, 256>>>(px, gcn_w[3], ph, NN, 128, 64, nullptr, nullptr);
    }
    gcn_agg<64><<<agg_blocks, 256>>>(ph, gcn_b[3], py, 3);
    bn_finalize<<<1, 128>>>(bn_g[3], bn_b[3], 64, 3);

    // ---- global mean pool with BN3 fused ----
    pool_acc<<<1024, 256>>>(py, batch, sc[3], sh[3]);
    pool_fin<<<(GG * 64 + 255) / 256, 256>>>((float*)d_out);
}

// round 6
// speedup vs baseline: 1.7829x; 1.0684x over previous
#include <cuda_runtime.h>
#include <math.h>
#include <mma.h>

using namespace nvcuda;

#define NN 100000
#define NPAD 100032            /* 1563 * 64 */
#define EE 1600000
#define GG 256
#define NB_SCAN 98             /* ceil(NN/1024) */

// ---------------- scratch (device globals; no allocation allowed) ----------
__device__ float g_x[NPAD * 128];
__device__ float g_y[NPAD * 128];
__device__ float g_h[NPAD * 128];
__device__ float g_hg[NPAD * 128];
__device__ int   g_cnt[NN];
__device__ int   g_offs[NN];
__device__ int   g_cursor[NN];
__device__ int   g_csrc[EE];
__device__ float g_dis[NN];
__device__ float g_an_src[NN * 4];
__device__ float g_an_dst[NN * 4];
__device__ float g_bnsum[4][128];
__device__ float g_bnsq[4][128];
__device__ float g_bnscale[4][128];
__device__ float g_bnshift[4][128];
__device__ int   g_bsum[128];
__device__ float g_pool[GG * 64];
__device__ float g_pcnt[GG];

__device__ __forceinline__ float lrelu(float v) { return v > 0.f ? v : 0.2f * v; }

// ---------------- init / CSR build ----------------------------------------
__global__ void zero_init() {
    int i = blockIdx.x * blockDim.x + threadIdx.x;
    int stride = gridDim.x * blockDim.x;
    for (int t = i; t < NN; t += stride) { g_cnt[t] = 0; g_cursor[t] = 0; }
    for (int t = i; t < GG * 64; t += stride) g_pool[t] = 0.f;
    for (int t = i; t < GG; t += stride) g_pcnt[t] = 0.f;
    for (int t = i; t < 4 * 128; t += stride) { (&g_bnsum[0][0])[t] = 0.f; (&g_bnsq[0][0])[t] = 0.f; }
}

__global__ void hist_k(const int* __restrict__ col, const int* __restrict__ batch) {
    int i = blockIdx.x * blockDim.x + threadIdx.x;
    int stride = gridDim.x * blockDim.x;
    for (int e = i; e < EE; e += stride)
        atomicAdd(&g_cnt[col[e]], 1);
    for (int t = i; t < NN; t += stride)
        atomicAdd(&g_pcnt[batch[t]], 1.f);
}

__global__ void scan1() {
    __shared__ int s[1024];
    int t = threadIdx.x;
    int gi = blockIdx.x * 1024 + t;
    int v = (gi < NN) ? g_cnt[gi] : 0;
    s[t] = v;
    for (int off = 1; off < 1024; off <<= 1) {
        __syncthreads();
        int u = (t >= off) ? s[t - off] : 0;
        __syncthreads();
        s[t] += u;
    }
    if (gi < NN) g_offs[gi] = s[t] - v;
    if (t == 1023) g_bsum[blockIdx.x] = s[1023];
}

__global__ void scan2() {
    int t = threadIdx.x;
    int lane = t & 31, w = t >> 5;
    int v = (t < NB_SCAN) ? g_bsum[t] : 0;
    int x = v;
#pragma unroll
    for (int off = 1; off < 32; off <<= 1) {
        int u = __shfl_up_sync(0xffffffffu, x, off);
        if (lane >= off) x += u;
    }
    __shared__ int wsum[4];
    if (lane == 31) wsum[w] = x;
    __syncthreads();
    int add = 0;
    for (int i = 0; i < w; i++) add += wsum[i];
    x += add;
    if (t < NB_SCAN) g_bsum[t] = x - v;
}

__global__ void scan3_dis() {
    int gi = blockIdx.x * 1024 + threadIdx.x;
    if (gi < NN) {
        g_offs[gi] += g_bsum[blockIdx.x];
        g_dis[gi] = rsqrtf((float)(g_cnt[gi] + 1));
    }
}

__global__ void scatter_k(const int* __restrict__ row, const int* __restrict__ col) {
    int i = blockIdx.x * blockDim.x + threadIdx.x;
    for (int e = i; e < EE; e += gridDim.x * blockDim.x) {
        int c = col[e];
        int pos = g_offs[c] + atomicAdd(&g_cursor[c], 1);
        g_csrc[pos] = row[e];
    }
}

// ---------------- GEMM: 3xTF32 WMMA, pre-split tiles -----------------------
// TRANS: 0 none | 1 A'=A*sc+sh | 2 A'=lrelu(A*sc+sh)
// EPI:   0 plain store | 1 +bias & BN stats | 2 store + GAT attn logits
#define BM 64
#define BN 64
#define BK 32

template <int TRANS, int EPI>
__global__ void gemm_tf32(const float* __restrict__ A, const float* __restrict__ W,
                          float* __restrict__ out, int n, int din, int dout,
                          const float* __restrict__ sc, const float* __restrict__ sh,
                          const float* __restrict__ bias, int layer,
                          const float* __restrict__ av_src, const float* __restrict__ av_dst) {
    __shared__ float As[2][BM][BK + 8];   // hi / lo  (also reused as epilogue buf)
    __shared__ float Bs[2][BK][BN + 8];
    int tid = threadIdx.x;
    int warp = tid >> 5;
    int wr = warp >> 1;
    int wc = warp & 1;
    int row0 = blockIdx.x * BM;
    int col0 = blockIdx.y * BN;

    wmma::fragment<wmma::accumulator, 16, 16, 8, float> acc[2];
    wmma::fill_fragment(acc[0], 0.f);
    wmma::fill_fragment(acc[1], 0.f);

    for (int k0 = 0; k0 < din; k0 += BK) {
#pragma unroll
        for (int v = tid; v < BM * 8; v += 256) {
            int r = v >> 3;
            int kk = (v & 7) * 4;
            float4 val = make_float4(0.f, 0.f, 0.f, 0.f);
            int grow = row0 + r, gk = k0 + kk;
            if (grow < n && gk < din) {
                val = *(const float4*)(A + (size_t)grow * din + gk);
                if (TRANS > 0) {
                    float4 s4 = *(const float4*)(sc + gk);
                    float4 h4 = *(const float4*)(sh + gk);
                    val.x = val.x * s4.x + h4.x;
                    val.y = val.y * s4.y + h4.y;
                    val.z = val.z * s4.z + h4.z;
                    val.w = val.w * s4.w + h4.w;
                    if (TRANS == 2) {
                        val.x = lrelu(val.x); val.y = lrelu(val.y);
                        val.z = lrelu(val.z); val.w = lrelu(val.w);
                    }
                }
            }
            float4 hi, lo;
            hi.x = wmma::__float_to_tf32(val.x); lo.x = wmma::__float_to_tf32(val.x - hi.x);
            hi.y = wmma::__float_to_tf32(val.y); lo.y = wmma::__float_to_tf32(val.y - hi.y);
            hi.z = wmma::__float_to_tf32(val.z); lo.z = wmma::__float_to_tf32(val.z - hi.z);
            hi.w = wmma::__float_to_tf32(val.w); lo.w = wmma::__float_to_tf32(val.w - hi.w);
            *(float4*)&As[0][r][kk] = hi;
            *(float4*)&As[1][r][kk] = lo;
        }
#pragma unroll
        for (int v = tid; v < BK * 16; v += 256) {
            int kk = v >> 4;
            int cc = (v & 15) * 4;
            float4 val = make_float4(0.f, 0.f, 0.f, 0.f);
            int gk = k0 + kk;
            if (gk < din)
                val = *(const float4*)(W + (size_t)gk * dout + col0 + cc);
            float4 hi, lo;
            hi.x = wmma::__float_to_tf32(val.x); lo.x = wmma::__float_to_tf32(val.x - hi.x);
            hi.y = wmma::__float_to_tf32(val.y); lo.y = wmma::__float_to_tf32(val.y - hi.y);
            hi.z = wmma::__float_to_tf32(val.z); lo.z = wmma::__float_to_tf32(val.z - hi.z);
            hi.w = wmma::__float_to_tf32(val.w); lo.w = wmma::__float_to_tf32(val.w - hi.w);
            *(float4*)&Bs[0][kk][cc] = hi;
            *(float4*)&Bs[1][kk][cc] = lo;
        }
        __syncthreads();

#pragma unroll
        for (int ks = 0; ks < BK; ks += 8) {
            wmma::fragment<wmma::matrix_a, 16, 16, 8, wmma::precision::tf32, wmma::row_major> a_hi, a_lo;
            wmma::load_matrix_sync(a_hi, &As[0][wr * 16][ks], BK + 8);
            wmma::load_matrix_sync(a_lo, &As[1][wr * 16][ks], BK + 8);
#pragma unroll
            for (int c = 0; c < 2; c++) {
                wmma::fragment<wmma::matrix_b, 16, 16, 8, wmma::precision::tf32, wmma::row_major> b_hi, b_lo;
                wmma::load_matrix_sync(b_hi, &Bs[0][ks][wc * 32 + c * 16], BN + 8);
                wmma::load_matrix_sync(b_lo, &Bs[1][ks][wc * 32 + c * 16], BN + 8);
                wmma::mma_sync(acc[c], a_hi, b_hi, acc[c]);
                wmma::mma_sync(acc[c], a_lo, b_hi, acc[c]);
                wmma::mma_sync(acc[c], a_hi, b_lo, acc[c]);
            }
        }
        __syncthreads();
    }

    if (EPI == 0) {
        int grow = row0 + wr * 16;
#pragma unroll
        for (int c = 0; c < 2; c++)
            wmma::store_matrix_sync(out + (size_t)grow * dout + col0 + wc * 32 + c * 16,
                                    acc[c], dout, wmma::mem_row_major);
    } else {
        // stage tile in smem (reuse As: 64 x 72 floats)
        float* buf = &As[0][0][0];
        const int LDB = 72;
#pragma unroll
        for (int c = 0; c < 2; c++)
            wmma::store_matrix_sync(buf + (wr * 16) * LDB + wc * 32 + c * 16,
                                    acc[c], LDB, wmma::mem_row_major);
        __syncthreads();
        int col = tid & 63;
        int part = tid >> 6;       // 0..3, each handles 16 rows of one column
        int gcol = col0 + col;
        if (EPI == 1) {
            float bv = bias[gcol];
            float s = 0.f, q = 0.f;
#pragma unroll
            for (int r = part * 16; r < part * 16 + 16; r++) {
                float v = buf[r * LDB + col] + bv;
                int grow = row0 + r;
                out[(size_t)grow * dout + gcol] = v;   // padded scratch: unguarded
                if (grow < n) { s += v; q += v * v; }
            }
            __shared__ float cS[64], cQ[64];
            if (tid < 64) { cS[tid] = 0.f; cQ[tid] = 0.f; }
            __syncthreads();
            atomicAdd(&cS[col], s);
            atomicAdd(&cQ[col], q);
            __syncthreads();
            if (tid < 64) {
                atomicAdd(&g_bnsum[layer][col0 + tid], cS[tid]);
                atomicAdd(&g_bnsq[layer][col0 + tid], cQ[tid]);
            }
        } else {  // EPI == 2: store hg + per-node attention logits
#pragma unroll
            for (int r = part * 16; r < part * 16 + 16; r++)
                out[(size_t)(row0 + r) * dout + gcol] = buf[r * LDB + col];
            int row = tid & 63;
            int c0 = part * 16;
            int C = dout >> 2;                 // channels per head (16 or 32)
            int hh = (col0 + c0) / C;          // 16-col strip lies in one head
            float s1 = 0.f, s2 = 0.f;
#pragma unroll
            for (int c = c0; c < c0 + 16; c++) {
                float v = buf[row * LDB + c];
                s1 += v * av_src[col0 + c];
                s2 += v * av_dst[col0 + c];
            }
            __shared__ float sA[64][4], sD[64][4];
            sA[tid >> 2][tid & 3] = 0.f;
            sD[tid >> 2][tid & 3] = 0.f;
            __syncthreads();
            atomicAdd(&sA[row][hh], s1);
            atomicAdd(&sD[row][hh], s2);
            __syncthreads();
            int hlo = col0 / C;
            int hcnt = 64 / C;                 // heads covered by this block
            if (tid < 64 * hcnt) {
                int r = tid / hcnt, k = tid % hcnt;
                int grow = row0 + r;
                if (grow < n) {
                    g_an_src[grow * 4 + hlo + k] = sA[r][hlo + k];
                    g_an_dst[grow * 4 + hlo + k] = sD[r][hlo + k];
                }
            }
        }
    }
}

// ---------------- pre-aggregation (before GEMM; linear commute) ------------
__global__ void pre_agg16(const float* __restrict__ x, float* __restrict__ z) {
    int i = blockIdx.x * blockDim.x + threadIdx.x;
    if (i >= NN) return;
    float di = g_dis[i];
    float ws = di * di;
    const float4* xi = (const float4*)(x + (size_t)i * 16);
    float4 a0 = xi[0], a1 = xi[1], a2 = xi[2], a3 = xi[3];
    a0.x *= ws; a0.y *= ws; a0.z *= ws; a0.w *= ws;
    a1.x *= ws; a1.y *= ws; a1.z *= ws; a1.w *= ws;
    a2.x *= ws; a2.y *= ws; a2.z *= ws; a2.w *= ws;
    a3.x *= ws; a3.y *= ws; a3.z *= ws; a3.w *= ws;
    int e = g_offs[i], end = e + g_cnt[i];
    for (; e < end; e++) {
        int j = g_csrc[e];
        float w = g_dis[j] * di;
        const float4* p = (const float4*)(x + (size_t)j * 16);
        float4 b0 = p[0], b1 = p[1], b2 = p[2], b3 = p[3];
        a0.x += b0.x * w; a0.y += b0.y * w; a0.z += b0.z * w; a0.w += b0.w * w;
        a1.x += b1.x * w; a1.y += b1.y * w; a1.z += b1.z * w; a1.w += b1.w * w;
        a2.x += b2.x * w; a2.y += b2.y * w; a2.z += b2.z * w; a2.w += b2.w * w;
        a3.x += b3.x * w; a3.y += b3.y * w; a3.z += b3.z * w; a3.w += b3.w * w;
    }
    float4* zo = (float4*)(z + (size_t)i * 16);
    zo[0] = a0; zo[1] = a1; zo[2] = a2; zo[3] = a3;
}

__global__ void pre_agg64(const float* __restrict__ x, float* __restrict__ z) {
    int warp = (blockIdx.x * blockDim.x + threadIdx.x) >> 5;
    int lane = threadIdx.x & 31;
    if (warp >= NN) return;
    int i = warp;
    float di = g_dis[i], ws = di * di;
    float a0 = x[(size_t)i * 64 + lane] * ws;
    float a1 = x[(size_t)i * 64 + 32 + lane] * ws;
    int e = g_offs[i], end = e + g_cnt[i];
    for (; e + 1 < end; e += 2) {
        int j0 = g_csrc[e], j1 = g_csrc[e + 1];
        float w0 = g_dis[j0] * di, w1 = g_dis[j1] * di;
        const float* p0 = x + (size_t)j0 * 64 + lane;
        const float* p1 = x + (size_t)j1 * 64 + lane;
        a0 += p0[0] * w0 + p1[0] * w1;
        a1 += p0[32] * w0 + p1[32] * w1;
    }
    if (e < end) {
        int j = g_csrc[e];
        float w = g_dis[j] * di;
        const float* p = x + (size_t)j * 64 + lane;
        a0 += p[0] * w;
        a1 += p[32] * w;
    }
    z[(size_t)i * 64 + lane] = a0;
    z[(size_t)i * 64 + 32 + lane] = a1;
}

// ---------------- GCN post-aggregation + fused BN stats --------------------
template <int DOUT>
__global__ void gcn_agg(const float* __restrict__ h, const float* __restrict__ bias,
                        float* __restrict__ y, int layer) {
    constexpr int CH = DOUT / 32;
    __shared__ float sS[DOUT], sQ[DOUT];
    int tid = threadIdx.x;
    for (int t = tid; t < DOUT; t += blockDim.x) { sS[t] = 0.f; sQ[t] = 0.f; }
    __syncthreads();
    int lane = tid & 31;
    int gw = (blockIdx.x * blockDim.x + tid) >> 5;
    int nw = (gridDim.x * blockDim.x) >> 5;
    float bs[CH];
#pragma unroll
    for (int cc = 0; cc < CH; cc++) bs[cc] = bias[cc * 32 + lane];
    float stS[CH], stQ[CH];
#pragma unroll
    for (int cc = 0; cc < CH; cc++) { stS[cc] = 0.f; stQ[cc] = 0.f; }

    for (int i = gw; i < NN; i += nw) {
        float di = g_dis[i];
        float ws = di * di;
        float acc[CH];
#pragma unroll
        for (int cc = 0; cc < CH; cc++)
            acc[cc] = h[(size_t)i * DOUT + cc * 32 + lane] * ws;
        int e = g_offs[i];
        int end = e + g_cnt[i];
        for (; e + 1 < end; e += 2) {
            int j0 = g_csrc[e], j1 = g_csrc[e + 1];
            float w0 = g_dis[j0] * di, w1 = g_dis[j1] * di;
            const float* p0 = h + (size_t)j0 * DOUT + lane;
            const float* p1 = h + (size_t)j1 * DOUT + lane;
#pragma unroll
            for (int cc = 0; cc < CH; cc++)
                acc[cc] += p0[cc * 32] * w0 + p1[cc * 32] * w1;
        }
        if (e < end) {
            int j = g_csrc[e];
            float w = g_dis[j] * di;
            const float* p = h + (size_t)j * DOUT + lane;
#pragma unroll
            for (int cc = 0; cc < CH; cc++)
                acc[cc] += p[cc * 32] * w;
        }
#pragma unroll
        for (int cc = 0; cc < CH; cc++) {
            float v = acc[cc] + bs[cc];
            y[(size_t)i * DOUT + cc * 32 + lane] = v;
            stS[cc] += v;
            stQ[cc] += v * v;
        }
    }
#pragma unroll
    for (int cc = 0; cc < CH; cc++) {
        atomicAdd(&sS[cc * 32 + lane], stS[cc]);
        atomicAdd(&sQ[cc * 32 + lane], stQ[cc]);
    }
    __syncthreads();
    for (int t = tid; t < DOUT; t += blockDim.x) {
        atomicAdd(&g_bnsum[layer][t], sS[t]);
        atomicAdd(&g_bnsq[layer][t], sQ[t]);
    }
}

// ---------------- BatchNorm affine table -----------------------------------
__global__ void bn_finalize(const float* __restrict__ g, const float* __restrict__ b,
                            int dout, int layer) {
    int c = threadIdx.x;
    if (c >= dout) return;
    float mean = g_bnsum[layer][c] * (1.f / NN);
    float var = g_bnsq[layer][c] * (1.f / NN) - mean * mean;
    float istd = rsqrtf(var + 1e-5f);
    float scv = g[c] * istd;
    g_bnscale[layer][c] = scv;
    g_bnshift[layer][c] = b[c] - mean * scv;
}

// ---------------- GAT aggregation ------------------------------------------
template <int DOUT>
__global__ void gat_agg(const float* __restrict__ hg, const float* __restrict__ yres,
                        const float* __restrict__ bias, float* __restrict__ xout,
                        const float* __restrict__ rsc, const float* __restrict__ rsh) {
    constexpr int CH = DOUT / 32;
    constexpr int C = DOUT / 4;
    int warp = (blockIdx.x * blockDim.x + threadIdx.x) >> 5;
    int lane = threadIdx.x & 31;
    if (warp >= NN) return;
    int i = warp;
    float4 asi = *(const float4*)&g_an_src[i * 4];
    float4 adi = *(const float4*)&g_an_dst[i * 4];
    float e0 = lrelu(asi.x + adi.x);
    float e1 = lrelu(asi.y + adi.y);
    float e2 = lrelu(asi.z + adi.z);
    float e3 = lrelu(asi.w + adi.w);
    float m0 = e0, m1 = e1, m2 = e2, m3 = e3;
    int s = g_offs[i], cnt = g_cnt[i];
    for (int e = s + lane; e < s + cnt; e += 32) {
        int j = g_csrc[e];
        float4 aj = *(const float4*)&g_an_src[j * 4];
        m0 = fmaxf(m0, lrelu(aj.x + adi.x));
        m1 = fmaxf(m1, lrelu(aj.y + adi.y));
        m2 = fmaxf(m2, lrelu(aj.z + adi.z));
        m3 = fmaxf(m3, lrelu(aj.w + adi.w));
    }
#pragma unroll
    for (int off = 16; off > 0; off >>= 1) {
        m0 = fmaxf(m0, __shfl_xor_sync(0xffffffffu, m0, off));
        m1 = fmaxf(m1, __shfl_xor_sync(0xffffffffu, m1, off));
        m2 = fmaxf(m2, __shfl_xor_sync(0xffffffffu, m2, off));
        m3 = fmaxf(m3, __shfl_xor_sync(0xffffffffu, m3, off));
    }
    float p0 = __expf(e0 - m0), p1 = __expf(e1 - m1);
    float p2 = __expf(e2 - m2), p3 = __expf(e3 - m3);
    float den0 = p0, den1 = p1, den2 = p2, den3 = p3;
    int hh[CH];
    float acc[CH];
#pragma unroll
    for (int cc = 0; cc < CH; cc++) {
        hh[cc] = (cc * 32 + lane) / C;
        float p = hh[cc] == 0 ? p0 : hh[cc] == 1 ? p1 : hh[cc] == 2 ? p2 : p3;
        acc[cc] = hg[(size_t)i * DOUT + cc * 32 + lane] * p;
    }
    int e = s, end = s + cnt;
    for (; e + 1 < end; e += 2) {
        int j0 = g_csrc[e], j1 = g_csrc[e + 1];
        float4 a0 = *(const float4*)&g_an_src[j0 * 4];
        float4 a1 = *(const float4*)&g_an_src[j1 * 4];
        float q00 = __expf(lrelu(a0.x + adi.x) - m0);
        float q01 = __expf(lrelu(a0.y + adi.y) - m1);
        float q02 = __expf(lrelu(a0.z + adi.z) - m2);
        float q03 = __expf(lrelu(a0.w + adi.w) - m3);
        float q10 = __expf(lrelu(a1.x + adi.x) - m0);
        float q11 = __expf(lrelu(a1.y + adi.y) - m1);
        float q12 = __expf(lrelu(a1.z + adi.z) - m2);
        float q13 = __expf(lrelu(a1.w + adi.w) - m3);
        den0 += q00 + q10; den1 += q01 + q11;
        den2 += q02 + q12; den3 += q03 + q13;
        const float* p0 = hg + (size_t)j0 * DOUT + lane;
        const float* p1 = hg + (size_t)j1 * DOUT + lane;
#pragma unroll
        for (int cc = 0; cc < CH; cc++) {
            float qa = hh[cc] == 0 ? q00 : hh[cc] == 1 ? q01 : hh[cc] == 2 ? q02 : q03;
            float qb = hh[cc] == 0 ? q10 : hh[cc] == 1 ? q11 : hh[cc] == 2 ? q12 : q13;
            acc[cc] += p0[cc * 32] * qa + p1[cc * 32] * qb;
        }
    }
    if (e < end) {
        int j = g_csrc[e];
        float4 aj = *(const float4*)&g_an_src[j * 4];
        float q0 = __expf(lrelu(aj.x + adi.x) - m0);
        float q1 = __expf(lrelu(aj.y + adi.y) - m1);
        float q2 = __expf(lrelu(aj.z + adi.z) - m2);
        float q3 = __expf(lrelu(aj.w + adi.w) - m3);
        den0 += q0; den1 += q1; den2 += q2; den3 += q3;
        const float* p = hg + (size_t)j * DOUT + lane;
#pragma unroll
        for (int cc = 0; cc < CH; cc++) {
            float q = hh[cc] == 0 ? q0 : hh[cc] == 1 ? q1 : hh[cc] == 2 ? q2 : q3;
            acc[cc] += p[cc * 32] * q;
        }
    }
#pragma unroll
    for (int cc = 0; cc < CH; cc++) {
        float d = hh[cc] == 0 ? den0 : hh[cc] == 1 ? den1 : hh[cc] == 2 ? den2 : den3;
        int col = cc * 32 + lane;
        float res = yres[(size_t)i * DOUT + col] * rsc[col] + rsh[col];  // BN fused
        float v = acc[cc] / d + bias[col] + res;
        xout[(size_t)i * DOUT + col] = lrelu(v);
    }
}

// ---------------- pooling (BN fused on read) -------------------------------
__global__ void pool_acc(const float* __restrict__ x, const int* __restrict__ batch,
                         const float* __restrict__ sc, const float* __restrict__ sh) {
    size_t total = (size_t)NN * 64;
    size_t i = (size_t)blockIdx.x * blockDim.x + threadIdx.x;
    size_t stride = (size_t)gridDim.x * blockDim.x;
    for (size_t t = i; t < total; t += stride) {
        int node = (int)(t >> 6);
        int c = (int)(t & 63);
        float v = x[t] * sc[c] + sh[c];
        atomicAdd(&g_pool[batch[node] * 64 + c], v);
    }
}

__global__ void pool_fin(float* __restrict__ out) {
    int i = blockIdx.x * blockDim.x + threadIdx.x;
    if (i < GG * 64) {
        int g = i >> 6;
        out[i] = g_pool[i] / fmaxf(g_pcnt[g], 1.f);
    }
}

// ---------------- host orchestration --------------------------------------
extern "C" void kernel_launch(void* const* d_in, const int* in_sizes, int n_in,
                              void* d_out, int out_size) {
    const float* x_in = (const float*)d_in[0];
    const int* ei = (const int*)d_in[1];
    const int* batch = (const int*)d_in[2];

    const float* gcn_w[4] = {(const float*)d_in[3], (const float*)d_in[7],
                             (const float*)d_in[11], (const float*)d_in[15]};
    const float* gcn_b[4] = {(const float*)d_in[4], (const float*)d_in[8],
                             (const float*)d_in[12], (const float*)d_in[16]};
    const float* bn_g[4] = {(const float*)d_in[5], (const float*)d_in[9],
                            (const float*)d_in[13], (const float*)d_in[17]};
    const float* bn_b[4] = {(const float*)d_in[6], (const float*)d_in[10],
                            (const float*)d_in[14], (const float*)d_in[18]};
    const float* gat_w[2] = {(const float*)d_in[19], (const float*)d_in[23]};
    const float* gat_as[2] = {(const float*)d_in[20], (const float*)d_in[24]};
    const float* gat_ad[2] = {(const float*)d_in[21], (const float*)d_in[25]};
    const float* gat_b[2] = {(const float*)d_in[22], (const float*)d_in[26]};

    float *px, *py, *ph, *phg, *psc, *psh;
    cudaGetSymbolAddress((void**)&px, g_x);
    cudaGetSymbolAddress((void**)&py, g_y);
    cudaGetSymbolAddress((void**)&ph, g_h);
    cudaGetSymbolAddress((void**)&phg, g_hg);
    cudaGetSymbolAddress((void**)&psc, g_bnscale);
    cudaGetSymbolAddress((void**)&psh, g_bnshift);
    const float* sc[4] = {psc, psc + 128, psc + 256, psc + 384};
    const float* sh[4] = {psh, psh + 128, psh + 256, psh + 384};

    const int warp_blocks = (NN * 32 + 255) / 256;
    const int agg_blocks = 148 * 8;
    const dim3 g1((NPAD + 63) / 64, 1);
    const dim3 g2((NPAD + 63) / 64, 2);

    // ---- CSR build ----
    zero_init<<<256, 256>>>();
    hist_k<<<1024, 256>>>(ei + EE, batch);
    scan1<<<NB_SCAN, 1024>>>();
    scan2<<<1, 128>>>();
    scan3_dis<<<NB_SCAN, 1024>>>();
    scatter_k<<<1024, 256>>>(ei, ei + EE);

    // ---- layer 0: pre-agg @16, GEMM 16->64 (+bias+stats), GAT ----
    pre_agg16<<<(NN + 255) / 256, 256>>>(x_in, ph);
    gemm_tf32<0, 1><<<g1, 256>>>(ph, gcn_w[0], py, NN, 16, 64,
                                 nullptr, nullptr, gcn_b[0], 0, nullptr, nullptr);
    bn_finalize<<<1, 128>>>(bn_g[0], bn_b[0], 64, 0);
    gemm_tf32<1, 2><<<g1, 256>>>(py, gat_w[0], phg, NN, 64, 64,
                                 sc[0], sh[0], nullptr, 0, gat_as[0], gat_ad[0]);
    gat_agg<64><<<warp_blocks, 256>>>(phg, py, gat_b[0], px, sc[0], sh[0]);

    // ---- layer 1: pre-agg @64, GEMM 64->128 (+bias+stats) ----
    pre_agg64<<<warp_blocks, 256>>>(px, ph);
    gemm_tf32<0, 1><<<g2, 256>>>(ph, gcn_w[1], py, NN, 64, 128,
                                 nullptr, nullptr, gcn_b[1], 1, nullptr, nullptr);
    bn_finalize<<<1, 128>>>(bn_g[1], bn_b[1], 128, 1);

    // ---- layer 2: GEMM(BN1+lrelu fused) 128->128, post-agg, GAT ----
    gemm_tf32<2, 0><<<g2, 256>>>(py, gcn_w[2], ph, NN, 128, 128,
                                 sc[1], sh[1], nullptr, 0, nullptr, nullptr);
    gcn_agg<128><<<agg_blocks, 256>>>(ph, gcn_b[2], py, 2);
    bn_finalize<<<1, 128>>>(bn_g[2], bn_b[2], 128, 2);
    gemm_tf32<1, 2><<<g2, 256>>>(py, gat_w[1], phg, NN, 128, 128,
                                 sc[2], sh[2], nullptr, 0, gat_as[1], gat_ad[1]);
    gat_agg<128><<<warp_blocks, 256>>>(phg, py, gat_b[1], px, sc[2], sh[2]);

    // ---- layer 3: GEMM 128->64, post-agg @64 ----
    gemm_tf32<0, 0><<<g1, 256>>>(px, gcn_w[3], ph, NN, 128, 64,
                                 nullptr, nullptr, nullptr, 0, nullptr, nullptr);
    gcn_agg<64><<<agg_blocks, 256>>>(ph, gcn_b[3], py, 3);
    bn_finalize<<<1, 128>>>(bn_g[3], bn_b[3], 64, 3);

    // ---- global mean pool (BN3 fused) ----
    pool_acc<<<1024, 256>>>(py, batch, sc[3], sh[3]);
    pool_fin<<<(GG * 64 + 255) / 256, 256>>>((float*)d_out);
}

// round 8
// speedup vs baseline: 1.7872x; 1.0024x over previous
#include <cuda_runtime.h>
#include <cuda_fp16.h>
#include <math.h>
#include <mma.h>

using namespace nvcuda;

#define NN 100000
#define NPAD 100032            /* 1563 * 64 */
#define EE 1600000
#define GG 256
#define NB_SCAN 98             /* ceil(NN/1024) */

// ---------------- scratch (device globals; no allocation allowed) ----------
__device__ float  g_x[NPAD * 128];      // fp32 scratch (GEMM in/out, residuals)
__device__ float  g_y[NPAD * 128];
__device__ float  g_h[NPAD * 128];
__device__ __half g_hh[NPAD * 128];     // half gather array: GCN h (layers 2,3)
__device__ __half g_hgh[NPAD * 128];    // half gather array: GAT hg
__device__ __half g_xh[NPAD * 64];      // half gather array: layer0 GAT output
__device__ int    g_cnt[NN];
__device__ int    g_offs[NN];
__device__ int    g_cursor[NN];
__device__ int    g_csrc[EE];
__device__ float  g_dis[NN];
__device__ float  g_an_src[NN * 4];
__device__ float  g_an_dst[NN * 4];
__device__ float  g_bnsum[4][128];
__device__ float  g_bnsq[4][128];
__device__ int    g_bsum[128];
__device__ float  g_pool[GG * 64];
__device__ float  g_pcnt[GG];

__device__ __forceinline__ float lrelu(float v) { return v > 0.f ? v : 0.2f * v; }

// BN affine from raw sums: v' = v*scv + shf
__device__ __forceinline__ void bn_affine(int layer, int c, const float* g, const float* b,
                                          float& scv, float& shf) {
    float mean = g_bnsum[layer][c] * (1.f / NN);
    float var = g_bnsq[layer][c] * (1.f / NN) - mean * mean;
    float istd = rsqrtf(var + 1e-5f);
    scv = g[c] * istd;
    shf = b[c] - mean * scv;
}

// ---------------- init / CSR build ----------------------------------------
__global__ void zero_init() {
    int i = blockIdx.x * blockDim.x + threadIdx.x;
    int stride = gridDim.x * blockDim.x;
    for (int t = i; t < NN; t += stride) { g_cnt[t] = 0; g_cursor[t] = 0; }
    for (int t = i; t < GG * 64; t += stride) g_pool[t] = 0.f;
    for (int t = i; t < GG; t += stride) g_pcnt[t] = 0.f;
    for (int t = i; t < 4 * 128; t += stride) { (&g_bnsum[0][0])[t] = 0.f; (&g_bnsq[0][0])[t] = 0.f; }
}

__global__ void hist_k(const int* __restrict__ col, const int* __restrict__ batch) {
    int i = blockIdx.x * blockDim.x + threadIdx.x;
    int stride = gridDim.x * blockDim.x;
    for (int e = i; e < EE; e += stride)
        atomicAdd(&g_cnt[col[e]], 1);
    for (int t = i; t < NN; t += stride)
        atomicAdd(&g_pcnt[batch[t]], 1.f);
}

__global__ void scan1() {
    __shared__ int s[1024];
    int t = threadIdx.x;
    int gi = blockIdx.x * 1024 + t;
    int v = (gi < NN) ? g_cnt[gi] : 0;
    s[t] = v;
    for (int off = 1; off < 1024; off <<= 1) {
        __syncthreads();
        int u = (t >= off) ? s[t - off] : 0;
        __syncthreads();
        s[t] += u;
    }
    if (gi < NN) g_offs[gi] = s[t] - v;
    if (t == 1023) g_bsum[blockIdx.x] = s[1023];
}

__global__ void scan2() {
    int t = threadIdx.x;
    int lane = t & 31, w = t >> 5;
    int v = (t < NB_SCAN) ? g_bsum[t] : 0;
    int x = v;
#pragma unroll
    for (int off = 1; off < 32; off <<= 1) {
        int u = __shfl_up_sync(0xffffffffu, x, off);
        if (lane >= off) x += u;
    }
    __shared__ int wsum[4];
    if (lane == 31) wsum[w] = x;
    __syncthreads();
    int add = 0;
    for (int i = 0; i < w; i++) add += wsum[i];
    x += add;
    if (t < NB_SCAN) g_bsum[t] = x - v;
}

__global__ void scan3_dis() {
    int gi = blockIdx.x * 1024 + threadIdx.x;
    if (gi < NN) {
        g_offs[gi] += g_bsum[blockIdx.x];
        g_dis[gi] = rsqrtf((float)(g_cnt[gi] + 1));
    }
}

__global__ void scatter_k(const int* __restrict__ row, const int* __restrict__ col) {
    int i = blockIdx.x * blockDim.x + threadIdx.x;
    for (int e = i; e < EE; e += gridDim.x * blockDim.x) {
        int c = col[e];
        int pos = g_offs[c] + atomicAdd(&g_cursor[c], 1);
        g_csrc[pos] = row[e];
    }
}

// ---------------- GEMM: 3xTF32 WMMA, pre-split tiles -----------------------
// TRANS: 0 none | 1 A'=A*bn | 2 A'=lrelu(A*bn)      (bn from g_bnsum[alayer])
// EPI:   1 fp32 store +bias & BN stats(slayer) | 2 half store + GAT logits | 3 half store
#define BM 64
#define BN 64
#define BK 32

template <int TRANS, int EPI>
__global__ void gemm_tf32(const float* __restrict__ A, const float* __restrict__ W,
                          float* __restrict__ out, __half* __restrict__ out_h,
                          int n, int din, int dout,
                          const float* __restrict__ bng, const float* __restrict__ bnb,
                          int alayer,
                          const float* __restrict__ bias, int slayer,
                          const float* __restrict__ av_src, const float* __restrict__ av_dst) {
    __shared__ float As[2][BM][BK + 8];   // hi / lo (reused as epilogue buf)
    __shared__ float Bs[2][BK][BN + 8];
    __shared__ float sc_s[128], sh_s[128];
    int tid = threadIdx.x;
    int warp = tid >> 5;
    int wr = warp >> 1;
    int wc = warp & 1;
    int row0 = blockIdx.x * BM;
    int col0 = blockIdx.y * BN;

    if (TRANS > 0) {
        for (int t = tid; t < din; t += 256) {
            float scv, shf;
            bn_affine(alayer, t, bng, bnb, scv, shf);
            sc_s[t] = scv;
            sh_s[t] = shf;
        }
        __syncthreads();
    }

    wmma::fragment<wmma::accumulator, 16, 16, 8, float> acc[2];
    wmma::fill_fragment(acc[0], 0.f);
    wmma::fill_fragment(acc[1], 0.f);

    for (int k0 = 0; k0 < din; k0 += BK) {
#pragma unroll
        for (int v = tid; v < BM * 8; v += 256) {
            int r = v >> 3;
            int kk = (v & 7) * 4;
            float4 val = make_float4(0.f, 0.f, 0.f, 0.f);
            int grow = row0 + r, gk = k0 + kk;
            if (grow < n && gk < din) {
                val = *(const float4*)(A + (size_t)grow * din + gk);
                if (TRANS > 0) {
                    val.x = val.x * sc_s[gk] + sh_s[gk];
                    val.y = val.y * sc_s[gk + 1] + sh_s[gk + 1];
                    val.z = val.z * sc_s[gk + 2] + sh_s[gk + 2];
                    val.w = val.w * sc_s[gk + 3] + sh_s[gk + 3];
                    if (TRANS == 2) {
                        val.x = lrelu(val.x); val.y = lrelu(val.y);
                        val.z = lrelu(val.z); val.w = lrelu(val.w);
                    }
                }
            }
            float4 hi, lo;
            hi.x = wmma::__float_to_tf32(val.x); lo.x = wmma::__float_to_tf32(val.x - hi.x);
            hi.y = wmma::__float_to_tf32(val.y); lo.y = wmma::__float_to_tf32(val.y - hi.y);
            hi.z = wmma::__float_to_tf32(val.z); lo.z = wmma::__float_to_tf32(val.z - hi.z);
            hi.w = wmma::__float_to_tf32(val.w); lo.w = wmma::__float_to_tf32(val.w - hi.w);
            *(float4*)&As[0][r][kk] = hi;
            *(float4*)&As[1][r][kk] = lo;
        }
#pragma unroll
        for (int v = tid; v < BK * 16; v += 256) {
            int kk = v >> 4;
            int cc = (v & 15) * 4;
            float4 val = make_float4(0.f, 0.f, 0.f, 0.f);
            int gk = k0 + kk;
            if (gk < din)
                val = *(const float4*)(W + (size_t)gk * dout + col0 + cc);
            float4 hi, lo;
            hi.x = wmma::__float_to_tf32(val.x); lo.x = wmma::__float_to_tf32(val.x - hi.x);
            hi.y = wmma::__float_to_tf32(val.y); lo.y = wmma::__float_to_tf32(val.y - hi.y);
            hi.z = wmma::__float_to_tf32(val.z); lo.z = wmma::__float_to_tf32(val.z - hi.z);
            hi.w = wmma::__float_to_tf32(val.w); lo.w = wmma::__float_to_tf32(val.w - hi.w);
            *(float4*)&Bs[0][kk][cc] = hi;
            *(float4*)&Bs[1][kk][cc] = lo;
        }
        __syncthreads();

#pragma unroll
        for (int ks = 0; ks < BK; ks += 8) {
            wmma::fragment<wmma::matrix_a, 16, 16, 8, wmma::precision::tf32, wmma::row_major> a_hi, a_lo;
            wmma::load_matrix_sync(a_hi, &As[0][wr * 16][ks], BK + 8);
            wmma::load_matrix_sync(a_lo, &As[1][wr * 16][ks], BK + 8);
#pragma unroll
            for (int c = 0; c < 2; c++) {
                wmma::fragment<wmma::matrix_b, 16, 16, 8, wmma::precision::tf32, wmma::row_major> b_hi, b_lo;
                wmma::load_matrix_sync(b_hi, &Bs[0][ks][wc * 32 + c * 16], BN + 8);
                wmma::load_matrix_sync(b_lo, &Bs[1][ks][wc * 32 + c * 16], BN + 8);
                wmma::mma_sync(acc[c], a_hi, b_hi, acc[c]);
                wmma::mma_sync(acc[c], a_lo, b_hi, acc[c]);
                wmma::mma_sync(acc[c], a_hi, b_lo, acc[c]);
            }
        }
        __syncthreads();
    }

    // stage tile in smem (reuse As: 64 rows x LDB)
    float* buf = &As[0][0][0];
    const int LDB = 72;
#pragma unroll
    for (int c = 0; c < 2; c++)
        wmma::store_matrix_sync(buf + (wr * 16) * LDB + wc * 32 + c * 16,
                                acc[c], LDB, wmma::mem_row_major);
    __syncthreads();

    if (EPI == 1) {
        int col = tid & 63;
        int part = tid >> 6;
        int gcol = col0 + col;
        float bv = bias[gcol];
        float s = 0.f, q = 0.f;
#pragma unroll
        for (int r = part * 16; r < part * 16 + 16; r++) {
            float v = buf[r * LDB + col] + bv;
            int grow = row0 + r;
            out[(size_t)grow * dout + gcol] = v;   // padded scratch: unguarded
            if (grow < n) { s += v; q += v * v; }
        }
        __shared__ float cS[64], cQ[64];
        if (tid < 64) { cS[tid] = 0.f; cQ[tid] = 0.f; }
        __syncthreads();
        atomicAdd(&cS[col], s);
        atomicAdd(&cQ[col], q);
        __syncthreads();
        if (tid < 64) {
            atomicAdd(&g_bnsum[slayer][col0 + tid], cS[tid]);
            atomicAdd(&g_bnsq[slayer][col0 + tid], cQ[tid]);
        }
    } else {
        // half2 store of the tile
        __half2* oh = (__half2*)out_h;
        int d2 = dout >> 1;
#pragma unroll
        for (int idx = tid; idx < 64 * 32; idx += 256) {
            int r = idx >> 5, c2 = idx & 31;
            float v0 = buf[r * LDB + 2 * c2];
            float v1 = buf[r * LDB + 2 * c2 + 1];
            oh[(size_t)(row0 + r) * d2 + (col0 >> 1) + c2] = __floats2half2_rn(v0, v1);
        }
        if (EPI == 2) {  // per-node GAT attention logits from the staged tile
            int row = tid & 63;
            int part = tid >> 6;
            int c0 = part * 16;
            int C = dout >> 2;
            int hh = (col0 + c0) / C;
            float s1 = 0.f, s2 = 0.f;
#pragma unroll
            for (int c = c0; c < c0 + 16; c++) {
                float v = buf[row * LDB + c];
                s1 += v * av_src[col0 + c];
                s2 += v * av_dst[col0 + c];
            }
            __shared__ float sA[64][4], sD[64][4];
            sA[tid >> 2][tid & 3] = 0.f;
            sD[tid >> 2][tid & 3] = 0.f;
            __syncthreads();
            atomicAdd(&sA[row][hh], s1);
            atomicAdd(&sD[row][hh], s2);
            __syncthreads();
            int hlo = col0 / C;
            int hcnt = 64 / C;
            if (tid < 64 * hcnt) {
                int r = tid / hcnt, k = tid % hcnt;
                int grow = row0 + r;
                if (grow < n) {
                    g_an_src[grow * 4 + hlo + k] = sA[r][hlo + k];
                    g_an_dst[grow * 4 + hlo + k] = sD[r][hlo + k];
                }
            }
        }
    }
}

// ---------------- pre-aggregation ------------------------------------------
__global__ void pre_agg16(const float* __restrict__ x, float* __restrict__ z) {
    int i = blockIdx.x * blockDim.x + threadIdx.x;
    if (i >= NN) return;
    float di = g_dis[i];
    float ws = di * di;
    const float4* xi = (const float4*)(x + (size_t)i * 16);
    float4 a0 = xi[0], a1 = xi[1], a2 = xi[2], a3 = xi[3];
    a0.x *= ws; a0.y *= ws; a0.z *= ws; a0.w *= ws;
    a1.x *= ws; a1.y *= ws; a1.z *= ws; a1.w *= ws;
    a2.x *= ws; a2.y *= ws; a2.z *= ws; a2.w *= ws;
    a3.x *= ws; a3.y *= ws; a3.z *= ws; a3.w *= ws;
    int e = g_offs[i], end = e + g_cnt[i];
    for (; e < end; e++) {
        int j = g_csrc[e];
        float w = g_dis[j] * di;
        const float4* p = (const float4*)(x + (size_t)j * 16);
        float4 b0 = p[0], b1 = p[1], b2 = p[2], b3 = p[3];
        a0.x += b0.x * w; a0.y += b0.y * w; a0.z += b0.z * w; a0.w += b0.w * w;
        a1.x += b1.x * w; a1.y += b1.y * w; a1.z += b1.z * w; a1.w += b1.w * w;
        a2.x += b2.x * w; a2.y += b2.y * w; a2.z += b2.z * w; a2.w += b2.w * w;
        a3.x += b3.x * w; a3.y += b3.y * w; a3.z += b3.z * w; a3.w += b3.w * w;
    }
    float4* zo = (float4*)(z + (size_t)i * 16);
    zo[0] = a0; zo[1] = a1; zo[2] = a2; zo[3] = a3;
}

// pre-agg at 64 dims, half2 input, fp32 output
__global__ void pre_agg64_h(const __half2* __restrict__ x2, float* __restrict__ z) {
    int warp = (blockIdx.x * blockDim.x + threadIdx.x) >> 5;
    int lane = threadIdx.x & 31;
    if (warp >= NN) return;
    int i = warp;
    float di = g_dis[i], ws = di * di;
    float2 hv = __half22float2(x2[(size_t)i * 32 + lane]);
    float a0 = hv.x * ws, a1 = hv.y * ws;
    int e = g_offs[i], end = e + g_cnt[i];
    for (; e + 1 < end; e += 2) {
        int j0 = g_csrc[e], j1 = g_csrc[e + 1];
        float w0 = g_dis[j0] * di, w1 = g_dis[j1] * di;
        float2 v0 = __half22float2(x2[(size_t)j0 * 32 + lane]);
        float2 v1 = __half22float2(x2[(size_t)j1 * 32 + lane]);
        a0 += v0.x * w0 + v1.x * w1;
        a1 += v0.y * w0 + v1.y * w1;
    }
    if (e < end) {
        int j = g_csrc[e];
        float w = g_dis[j] * di;
        float2 v = __half22float2(x2[(size_t)j * 32 + lane]);
        a0 += v.x * w;
        a1 += v.y * w;
    }
    *(float2*)&z[(size_t)i * 64 + 2 * lane] = make_float2(a0, a1);
}

// ---------------- GCN post-aggregation (half gather) + BN stats ------------
template <int DOUT>
__global__ void gcn_agg_h(const __half2* __restrict__ h2, const float* __restrict__ bias,
                          float* __restrict__ y, int layer) {
    constexpr int CC = DOUT / 64;      // half2 chunks per lane
    constexpr int D2 = DOUT / 2;
    __shared__ float sS[DOUT], sQ[DOUT];
    int tid = threadIdx.x;
    for (int t = tid; t < DOUT; t += blockDim.x) { sS[t] = 0.f; sQ[t] = 0.f; }
    __syncthreads();
    int lane = tid & 31;
    int gw = (blockIdx.x * blockDim.x + tid) >> 5;
    int nw = (gridDim.x * blockDim.x) >> 5;
    float b0[CC], b1[CC];
#pragma unroll
    for (int cc = 0; cc < CC; cc++) {
        int col = cc * 64 + 2 * lane;
        b0[cc] = bias[col]; b1[cc] = bias[col + 1];
    }
    float s0[CC], s1[CC], q0[CC], q1[CC];
#pragma unroll
    for (int cc = 0; cc < CC; cc++) { s0[cc] = s1[cc] = q0[cc] = q1[cc] = 0.f; }

    for (int i = gw; i < NN; i += nw) {
        float di = g_dis[i];
        float ws = di * di;
        float a0[CC], a1[CC];
#pragma unroll
        for (int cc = 0; cc < CC; cc++) {
            float2 v = __half22float2(h2[(size_t)i * D2 + cc * 32 + lane]);
            a0[cc] = v.x * ws; a1[cc] = v.y * ws;
        }
        int e = g_offs[i];
        int end = e + g_cnt[i];
        for (; e + 1 < end; e += 2) {
            int j0 = g_csrc[e], j1 = g_csrc[e + 1];
            float w0 = g_dis[j0] * di, w1 = g_dis[j1] * di;
#pragma unroll
            for (int cc = 0; cc < CC; cc++) {
                float2 v0 = __half22float2(h2[(size_t)j0 * D2 + cc * 32 + lane]);
                float2 v1 = __half22float2(h2[(size_t)j1 * D2 + cc * 32 + lane]);
                a0[cc] += v0.x * w0 + v1.x * w1;
                a1[cc] += v0.y * w0 + v1.y * w1;
            }
        }
        if (e < end) {
            int j = g_csrc[e];
            float w = g_dis[j] * di;
#pragma unroll
            for (int cc = 0; cc < CC; cc++) {
                float2 v = __half22float2(h2[(size_t)j * D2 + cc * 32 + lane]);
                a0[cc] += v.x * w;
                a1[cc] += v.y * w;
            }
        }
#pragma unroll
        for (int cc = 0; cc < CC; cc++) {
            float v0 = a0[cc] + b0[cc];
            float v1 = a1[cc] + b1[cc];
            int col = cc * 64 + 2 * lane;
            *(float2*)&y[(size_t)i * DOUT + col] = make_float2(v0, v1);
            s0[cc] += v0; q0[cc] += v0 * v0;
            s1[cc] += v1; q1[cc] += v1 * v1;
        }
    }
#pragma unroll
    for (int cc = 0; cc < CC; cc++) {
        int col = cc * 64 + 2 * lane;
        atomicAdd(&sS[col], s0[cc]);
        atomicAdd(&sQ[col], q0[cc]);
        atomicAdd(&sS[col + 1], s1[cc]);
        atomicAdd(&sQ[col + 1], q1[cc]);
    }
    __syncthreads();
    for (int t = tid; t < DOUT; t += blockDim.x) {
        atomicAdd(&g_bnsum[layer][t], sS[t]);
        atomicAdd(&g_bnsq[layer][t], sQ[t]);
    }
}

// ---------------- GAT aggregation (half gather) ----------------------------
// OUTH=1: write half2 output (xout_h); OUTH=0: write fp32 (xout)
template <int DOUT, int OUTH>
__global__ void gat_agg_h(const __half2* __restrict__ hg2, const float* __restrict__ yres,
                          const float* __restrict__ bias,
                          float* __restrict__ xout, __half2* __restrict__ xout_h,
                          const float* __restrict__ bng, const float* __restrict__ bnb,
                          int layer) {
    constexpr int CC = DOUT / 64;
    constexpr int D2 = DOUT / 2;
    constexpr int C = DOUT / 4;
    int warp = (blockIdx.x * blockDim.x + threadIdx.x) >> 5;
    int lane = threadIdx.x & 31;
    if (warp >= NN) return;
    int i = warp;
    float4 asi = *(const float4*)&g_an_src[i * 4];
    float4 adi = *(const float4*)&g_an_dst[i * 4];
    float e0 = lrelu(asi.x + adi.x);
    float e1 = lrelu(asi.y + adi.y);
    float e2 = lrelu(asi.z + adi.z);
    float e3 = lrelu(asi.w + adi.w);
    float m0 = e0, m1 = e1, m2 = e2, m3 = e3;
    int s = g_offs[i], cnt = g_cnt[i];
    for (int e = s + lane; e < s + cnt; e += 32) {
        int j = g_csrc[e];
        float4 aj = *(const float4*)&g_an_src[j * 4];
        m0 = fmaxf(m0, lrelu(aj.x + adi.x));
        m1 = fmaxf(m1, lrelu(aj.y + adi.y));
        m2 = fmaxf(m2, lrelu(aj.z + adi.z));
        m3 = fmaxf(m3, lrelu(aj.w + adi.w));
    }
#pragma unroll
    for (int off = 16; off > 0; off >>= 1) {
        m0 = fmaxf(m0, __shfl_xor_sync(0xffffffffu, m0, off));
        m1 = fmaxf(m1, __shfl_xor_sync(0xffffffffu, m1, off));
        m2 = fmaxf(m2, __shfl_xor_sync(0xffffffffu, m2, off));
        m3 = fmaxf(m3, __shfl_xor_sync(0xffffffffu, m3, off));
    }
    float p0 = __expf(e0 - m0), p1 = __expf(e1 - m1);
    float p2 = __expf(e2 - m2), p3 = __expf(e3 - m3);
    float den0 = p0, den1 = p1, den2 = p2, den3 = p3;
    int hh[CC];
    float a0[CC], a1[CC];
#pragma unroll
    for (int cc = 0; cc < CC; cc++) {
        int col = cc * 64 + 2 * lane;
        hh[cc] = col / C;
        float p = hh[cc] == 0 ? p0 : hh[cc] == 1 ? p1 : hh[cc] == 2 ? p2 : p3;
        float2 hv = __half22float2(hg2[(size_t)i * D2 + cc * 32 + lane]);
        a0[cc] = hv.x * p;
        a1[cc] = hv.y * p;
    }
    int e = s, end = s + cnt;
    for (; e + 1 < end; e += 2) {
        int j0 = g_csrc[e], j1 = g_csrc[e + 1];
        float4 aj0 = *(const float4*)&g_an_src[j0 * 4];
        float4 aj1 = *(const float4*)&g_an_src[j1 * 4];
        float q00 = __expf(lrelu(aj0.x + adi.x) - m0);
        float q01 = __expf(lrelu(aj0.y + adi.y) - m1);
        float q02 = __expf(lrelu(aj0.z + adi.z) - m2);
        float q03 = __expf(lrelu(aj0.w + adi.w) - m3);
        float q10 = __expf(lrelu(aj1.x + adi.x) - m0);
        float q11 = __expf(lrelu(aj1.y + adi.y) - m1);
        float q12 = __expf(lrelu(aj1.z + adi.z) - m2);
        float q13 = __expf(lrelu(aj1.w + adi.w) - m3);
        den0 += q00 + q10; den1 += q01 + q11;
        den2 += q02 + q12; den3 += q03 + q13;
#pragma unroll
        for (int cc = 0; cc < CC; cc++) {
            float qa = hh[cc] == 0 ? q00 : hh[cc] == 1 ? q01 : hh[cc] == 2 ? q02 : q03;
            float qb = hh[cc] == 0 ? q10 : hh[cc] == 1 ? q11 : hh[cc] == 2 ? q12 : q13;
            float2 v0 = __half22float2(hg2[(size_t)j0 * D2 + cc * 32 + lane]);
            float2 v1 = __half22float2(hg2[(size_t)j1 * D2 + cc * 32 + lane]);
            a0[cc] += v0.x * qa + v1.x * qb;
            a1[cc] += v0.y * qa + v1.y * qb;
        }
    }
    if (e < end) {
        int j = g_csrc[e];
        float4 aj = *(const float4*)&g_an_src[j * 4];
        float q0 = __expf(lrelu(aj.x + adi.x) - m0);
        float q1 = __expf(lrelu(aj.y + adi.y) - m1);
        float q2 = __expf(lrelu(aj.z + adi.z) - m2);
        float q3 = __expf(lrelu(aj.w + adi.w) - m3);
        den0 += q0; den1 += q1; den2 += q2; den3 += q3;
#pragma unroll
        for (int cc = 0; cc < CC; cc++) {
            float q = hh[cc] == 0 ? q0 : hh[cc] == 1 ? q1 : hh[cc] == 2 ? q2 : q3;
            float2 v = __half22float2(hg2[(size_t)j * D2 + cc * 32 + lane]);
            a0[cc] += v.x * q;
            a1[cc] += v.y * q;
        }
    }
#pragma unroll
    for (int cc = 0; cc < CC; cc++) {
        float d = hh[cc] == 0 ? den0 : hh[cc] == 1 ? den1 : hh[cc] == 2 ? den2 : den3;
        int col = cc * 64 + 2 * lane;
        float sc0, sf0, sc1, sf1;
        bn_affine(layer, col, bng, bnb, sc0, sf0);
        bn_affine(layer, col + 1, bng, bnb, sc1, sf1);
        float2 rv = *(const float2*)&yres[(size_t)i * DOUT + col];
        float v0 = lrelu(a0[cc] / d + bias[col] + rv.x * sc0 + sf0);
        float v1 = lrelu(a1[cc] / d + bias[col + 1] + rv.y * sc1 + sf1);
        if (OUTH)
            xout_h[(size_t)i * D2 + cc * 32 + lane] = __floats2half2_rn(v0, v1);
        else
            *(float2*)&xout[(size_t)i * DOUT + col] = make_float2(v0, v1);
    }
}

// ---------------- pooling (BN fused via raw sums) --------------------------
__global__ void pool_acc(const float* __restrict__ x, const int* __restrict__ batch,
                         const float* __restrict__ bng, const float* __restrict__ bnb) {
    __shared__ float psc[64], psh[64];
    if (threadIdx.x < 64) {
        float scv, shf;
        bn_affine(3, threadIdx.x, bng, bnb, scv, shf);
        psc[threadIdx.x] = scv;
        psh[threadIdx.x] = shf;
    }
    __syncthreads();
    size_t total = (size_t)NN * 64;
    size_t i = (size_t)blockIdx.x * blockDim.x + threadIdx.x;
    size_t stride = (size_t)gridDim.x * blockDim.x;
    for (size_t t = i; t < total; t += stride) {
        int node = (int)(t >> 6);
        int c = (int)(t & 63);
        float v = x[t] * psc[c] + psh[c];
        atomicAdd(&g_pool[batch[node] * 64 + c], v);
    }
}

__global__ void pool_fin(float* __restrict__ out) {
    int i = blockIdx.x * blockDim.x + threadIdx.x;
    if (i < GG * 64) {
        int g = i >> 6;
        out[i] = g_pool[i] / fmaxf(g_pcnt[g], 1.f);
    }
}

// ---------------- host orchestration --------------------------------------
extern "C" void kernel_launch(void* const* d_in, const int* in_sizes, int n_in,
                              void* d_out, int out_size) {
    const float* x_in = (const float*)d_in[0];
    const int* ei = (const int*)d_in[1];
    const int* batch = (const int*)d_in[2];

    const float* gcn_w[4] = {(const float*)d_in[3], (const float*)d_in[7],
                             (const float*)d_in[11], (const float*)d_in[15]};
    const float* gcn_b[4] = {(const float*)d_in[4], (const float*)d_in[8],
                             (const float*)d_in[12], (const float*)d_in[16]};
    const float* bn_g[4] = {(const float*)d_in[5], (const float*)d_in[9],
                            (const float*)d_in[13], (const float*)d_in[17]};
    const float* bn_b[4] = {(const float*)d_in[6], (const float*)d_in[10],
                            (const float*)d_in[14], (const float*)d_in[18]};
    const float* gat_w[2] = {(const float*)d_in[19], (const float*)d_in[23]};
    const float* gat_as[2] = {(const float*)d_in[20], (const float*)d_in[24]};
    const float* gat_ad[2] = {(const float*)d_in[21], (const float*)d_in[25]};
    const float* gat_b[2] = {(const float*)d_in[22], (const float*)d_in[26]};

    float *px, *py, *ph;
    __half *phh, *phgh, *pxh;
    cudaGetSymbolAddress((void**)&px, g_x);
    cudaGetSymbolAddress((void**)&py, g_y);
    cudaGetSymbolAddress((void**)&ph, g_h);
    cudaGetSymbolAddress((void**)&phh, g_hh);
    cudaGetSymbolAddress((void**)&phgh, g_hgh);
    cudaGetSymbolAddress((void**)&pxh, g_xh);

    const int warp_blocks = (NN * 32 + 255) / 256;
    const int agg_blocks = 148 * 8;
    const dim3 g1((NPAD + 63) / 64, 1);
    const dim3 g2((NPAD + 63) / 64, 2);

    // ---- CSR build ----
    zero_init<<<256, 256>>>();
    hist_k<<<1024, 256>>>(ei + EE, batch);
    scan1<<<NB_SCAN, 1024>>>();
    scan2<<<1, 128>>>();
    scan3_dis<<<NB_SCAN, 1024>>>();
    scatter_k<<<1024, 256>>>(ei, ei + EE);

    // ---- layer 0: pre-agg @16, GEMM 16->64 (+bias+stats L0), GAT ----
    pre_agg16<<<(NN + 255) / 256, 256>>>(x_in, ph);
    gemm_tf32<0, 1><<<g1, 256>>>(ph, gcn_w[0], py, nullptr, NN, 16, 64,
                                 nullptr, nullptr, 0, gcn_b[0], 0, nullptr, nullptr);
    gemm_tf32<1, 2><<<g1, 256>>>(py, gat_w[0], nullptr, phgh, NN, 64, 64,
                                 bn_g[0], bn_b[0], 0, nullptr, 0, gat_as[0], gat_ad[0]);
    gat_agg_h<64, 1><<<warp_blocks, 256>>>((const __half2*)phgh, py, gat_b[0],
                                           nullptr, (__half2*)pxh,
                                           bn_g[0], bn_b[0], 0);

    // ---- layer 1: pre-agg @64 (half in), GEMM 64->128 (+bias+stats L1) ----
    pre_agg64_h<<<warp_blocks, 256>>>((const __half2*)pxh, ph);
    gemm_tf32<0, 1><<<g2, 256>>>(ph, gcn_w[1], py, nullptr, NN, 64, 128,
                                 nullptr, nullptr, 0, gcn_b[1], 1, nullptr, nullptr);

    // ---- layer 2: GEMM(BN1+lrelu) 128->128 -> half, post-agg, GAT ----
    gemm_tf32<2, 3><<<g2, 256>>>(py, gcn_w[2], nullptr, phh, NN, 128, 128,
                                 bn_g[1], bn_b[1], 1, nullptr, 0, nullptr, nullptr);
    gcn_agg_h<128><<<agg_blocks, 256>>>((const __half2*)phh, gcn_b[2], py, 2);
    gemm_tf32<1, 2><<<g2, 256>>>(py, gat_w[1], nullptr, phgh, NN, 128, 128,
                                 bn_g[2], bn_b[2], 2, nullptr, 0, gat_as[1], gat_ad[1]);
    gat_agg_h<128, 0><<<warp_blocks, 256>>>((const __half2*)phgh, py, gat_b[1],
                                            px, nullptr, bn_g[2], bn_b[2], 2);

    // ---- layer 3: GEMM 128->64 -> half, post-agg @64 ----
    gemm_tf32<0, 3><<<g1, 256>>>(px, gcn_w[3], nullptr, phh, NN, 128, 64,
                                 nullptr, nullptr, 0, nullptr, 0, nullptr, nullptr);
    gcn_agg_h<64><<<agg_blocks, 256>>>((const __half2*)phh, gcn_b[3], py, 3);

    // ---- global mean pool (BN3 fused) ----
    pool_acc<<<1024, 256>>>(py, batch, bn_g[3], bn_b[3]);
    pool_fin<<<(GG * 64 + 255) / 256, 256>>>((float*)d_out);
}

// round 9
// speedup vs baseline: 2.0081x; 1.1236x over previous
#include <cuda_runtime.h>
#include <cuda_fp16.h>
#include <math.h>
#include <mma.h>

using namespace nvcuda;

#define NN 100000
#define NPAD 100032            /* 1563 * 64 */
#define EE 1600000
#define GG 256
#define NB_SCAN 98             /* ceil(NN/1024) */

// ---------------- scratch (device globals; no allocation allowed) ----------
__device__ float  g_x[NPAD * 128];
__device__ float  g_y[NPAD * 128];
__device__ float  g_h[NPAD * 128];
__device__ __half g_hh[NPAD * 128];     // half gather array: GCN h
__device__ __half g_hgh[NPAD * 128];    // half gather array: GAT hg
__device__ __half g_xh[NPAD * 64];      // half gather array: layer0 GAT output
__device__ int    g_cnt[NN];
__device__ int    g_offs[NN];
__device__ int    g_cursor[NN];
__device__ int    g_csrc[EE];
__device__ float  g_ew[EE];             // per-edge GCN norm dis[src]*dis[dst]
__device__ float  g_dis[NN];
__device__ float  g_an_src[NN * 4];
__device__ float  g_an_dst[NN * 4];
__device__ float  g_bnsum[4][128];
__device__ float  g_bnsq[4][128];
__device__ int    g_bsum[128];
__device__ float  g_pool[GG * 64];
__device__ float  g_pcnt[GG];

__device__ __forceinline__ float lrelu(float v) { return v > 0.f ? v : 0.2f * v; }

__device__ __forceinline__ void bn_affine(int layer, int c, const float* g, const float* b,
                                          float& scv, float& shf) {
    float mean = g_bnsum[layer][c] * (1.f / NN);
    float var = g_bnsq[layer][c] * (1.f / NN) - mean * mean;
    float istd = rsqrtf(var + 1e-5f);
    scv = g[c] * istd;
    shf = b[c] - mean * scv;
}

// ---------------- init / CSR build ----------------------------------------
__global__ void zero_init() {
    int i = blockIdx.x * blockDim.x + threadIdx.x;
    int stride = gridDim.x * blockDim.x;
    for (int t = i; t < NN; t += stride) { g_cnt[t] = 0; g_cursor[t] = 0; }
    for (int t = i; t < GG * 64; t += stride) g_pool[t] = 0.f;
    for (int t = i; t < GG; t += stride) g_pcnt[t] = 0.f;
    for (int t = i; t < 4 * 128; t += stride) { (&g_bnsum[0][0])[t] = 0.f; (&g_bnsq[0][0])[t] = 0.f; }
}

__global__ void hist_k(const int* __restrict__ col, const int* __restrict__ batch) {
    int i = blockIdx.x * blockDim.x + threadIdx.x;
    int stride = gridDim.x * blockDim.x;
    for (int e = i; e < EE; e += stride)
        atomicAdd(&g_cnt[col[e]], 1);
    for (int t = i; t < NN; t += stride)
        atomicAdd(&g_pcnt[batch[t]], 1.f);
}

__global__ void scan1() {
    __shared__ int s[1024];
    int t = threadIdx.x;
    int gi = blockIdx.x * 1024 + t;
    int v = (gi < NN) ? g_cnt[gi] : 0;
    s[t] = v;
    for (int off = 1; off < 1024; off <<= 1) {
        __syncthreads();
        int u = (t >= off) ? s[t - off] : 0;
        __syncthreads();
        s[t] += u;
    }
    if (gi < NN) g_offs[gi] = s[t] - v;    // exclusive within chunk
    if (t == 1023) g_bsum[blockIdx.x] = s[1023];   // chunk total
}

// fused: add cross-chunk base (scan of g_bsum, computed in-block) + dis
__global__ void scan3_dis() {
    __shared__ int sbase;
    int t = threadIdx.x;
    if (t == 0) sbase = 0;
    __syncthreads();
    int p = (t < blockIdx.x) ? g_bsum[t] : 0;   // blockIdx.x <= 97 < 1024
#pragma unroll
    for (int off = 16; off > 0; off >>= 1)
        p += __shfl_xor_sync(0xffffffffu, p, off);
    if ((t & 31) == 0 && p) atomicAdd(&sbase, p);
    __syncthreads();
    int gi = blockIdx.x * 1024 + t;
    if (gi < NN) {
        g_offs[gi] += sbase;
        g_dis[gi] = rsqrtf((float)(g_cnt[gi] + 1));
    }
}

__global__ void scatter_k(const int* __restrict__ row, const int* __restrict__ col) {
    int i = blockIdx.x * blockDim.x + threadIdx.x;
    for (int e = i; e < EE; e += gridDim.x * blockDim.x) {
        int c = col[e];
        int r = row[e];
        int pos = g_offs[c] + atomicAdd(&g_cursor[c], 1);
        g_csrc[pos] = r;
        g_ew[pos] = g_dis[r] * g_dis[c];
    }
}

// ---------------- GEMM: 3xTF32 WMMA, pre-split tiles -----------------------
// TRANS: 0 none | 1 A'=A*bn | 2 A'=lrelu(A*bn)
// EPI:   1 fp32 store +bias & BN stats(slayer) | 2 half store + GAT logits | 3 half store
#define BM 64
#define BN 64
#define BK 32

template <int TRANS, int EPI>
__global__ void gemm_tf32(const float* __restrict__ A, const float* __restrict__ W,
                          float* __restrict__ out, __half* __restrict__ out_h,
                          int n, int din, int dout,
                          const float* __restrict__ bng, const float* __restrict__ bnb,
                          int alayer,
                          const float* __restrict__ bias, int slayer,
                          const float* __restrict__ av_src, const float* __restrict__ av_dst) {
    __shared__ float As[2][BM][BK + 8];
    __shared__ float Bs[2][BK][BN + 8];
    __shared__ float sc_s[128], sh_s[128];
    int tid = threadIdx.x;
    int warp = tid >> 5;
    int wr = warp >> 1;
    int wc = warp & 1;
    int row0 = blockIdx.x * BM;
    int col0 = blockIdx.y * BN;

    if (TRANS > 0) {
        for (int t = tid; t < din; t += 256) {
            float scv, shf;
            bn_affine(alayer, t, bng, bnb, scv, shf);
            sc_s[t] = scv;
            sh_s[t] = shf;
        }
        __syncthreads();
    }

    wmma::fragment<wmma::accumulator, 16, 16, 8, float> acc[2];
    wmma::fill_fragment(acc[0], 0.f);
    wmma::fill_fragment(acc[1], 0.f);

    for (int k0 = 0; k0 < din; k0 += BK) {
#pragma unroll
        for (int v = tid; v < BM * 8; v += 256) {
            int r = v >> 3;
            int kk = (v & 7) * 4;
            float4 val = make_float4(0.f, 0.f, 0.f, 0.f);
            int grow = row0 + r, gk = k0 + kk;
            if (grow < n && gk < din) {
                val = *(const float4*)(A + (size_t)grow * din + gk);
                if (TRANS > 0) {
                    val.x = val.x * sc_s[gk] + sh_s[gk];
                    val.y = val.y * sc_s[gk + 1] + sh_s[gk + 1];
                    val.z = val.z * sc_s[gk + 2] + sh_s[gk + 2];
                    val.w = val.w * sc_s[gk + 3] + sh_s[gk + 3];
                    if (TRANS == 2) {
                        val.x = lrelu(val.x); val.y = lrelu(val.y);
                        val.z = lrelu(val.z); val.w = lrelu(val.w);
                    }
                }
            }
            float4 hi, lo;
            hi.x = wmma::__float_to_tf32(val.x); lo.x = wmma::__float_to_tf32(val.x - hi.x);
            hi.y = wmma::__float_to_tf32(val.y); lo.y = wmma::__float_to_tf32(val.y - hi.y);
            hi.z = wmma::__float_to_tf32(val.z); lo.z = wmma::__float_to_tf32(val.z - hi.z);
            hi.w = wmma::__float_to_tf32(val.w); lo.w = wmma::__float_to_tf32(val.w - hi.w);
            *(float4*)&As[0][r][kk] = hi;
            *(float4*)&As[1][r][kk] = lo;
        }
#pragma unroll
        for (int v = tid; v < BK * 16; v += 256) {
            int kk = v >> 4;
            int cc = (v & 15) * 4;
            float4 val = make_float4(0.f, 0.f, 0.f, 0.f);
            int gk = k0 + kk;
            if (gk < din)
                val = *(const float4*)(W + (size_t)gk * dout + col0 + cc);
            float4 hi, lo;
            hi.x = wmma::__float_to_tf32(val.x); lo.x = wmma::__float_to_tf32(val.x - hi.x);
            hi.y = wmma::__float_to_tf32(val.y); lo.y = wmma::__float_to_tf32(val.y - hi.y);
            hi.z = wmma::__float_to_tf32(val.z); lo.z = wmma::__float_to_tf32(val.z - hi.z);
            hi.w = wmma::__float_to_tf32(val.w); lo.w = wmma::__float_to_tf32(val.w - hi.w);
            *(float4*)&Bs[0][kk][cc] = hi;
            *(float4*)&Bs[1][kk][cc] = lo;
        }
        __syncthreads();

#pragma unroll
        for (int ks = 0; ks < BK; ks += 8) {
            wmma::fragment<wmma::matrix_a, 16, 16, 8, wmma::precision::tf32, wmma::row_major> a_hi, a_lo;
            wmma::load_matrix_sync(a_hi, &As[0][wr * 16][ks], BK + 8);
            wmma::load_matrix_sync(a_lo, &As[1][wr * 16][ks], BK + 8);
#pragma unroll
            for (int c = 0; c < 2; c++) {
                wmma::fragment<wmma::matrix_b, 16, 16, 8, wmma::precision::tf32, wmma::row_major> b_hi, b_lo;
                wmma::load_matrix_sync(b_hi, &Bs[0][ks][wc * 32 + c * 16], BN + 8);
                wmma::load_matrix_sync(b_lo, &Bs[1][ks][wc * 32 + c * 16], BN + 8);
                wmma::mma_sync(acc[c], a_hi, b_hi, acc[c]);
                wmma::mma_sync(acc[c], a_lo, b_hi, acc[c]);
                wmma::mma_sync(acc[c], a_hi, b_lo, acc[c]);
            }
        }
        __syncthreads();
    }

    float* buf = &As[0][0][0];
    const int LDB = 72;
#pragma unroll
    for (int c = 0; c < 2; c++)
        wmma::store_matrix_sync(buf + (wr * 16) * LDB + wc * 32 + c * 16,
                                acc[c], LDB, wmma::mem_row_major);
    __syncthreads();

    if (EPI == 1) {
        int col = tid & 63;
        int part = tid >> 6;
        int gcol = col0 + col;
        float bv = bias[gcol];
        float s = 0.f, q = 0.f;
#pragma unroll
        for (int r = part * 16; r < part * 16 + 16; r++) {
            float v = buf[r * LDB + col] + bv;
            int grow = row0 + r;
            out[(size_t)grow * dout + gcol] = v;
            if (grow < n) { s += v; q += v * v; }
        }
        __shared__ float cS[64], cQ[64];
        if (tid < 64) { cS[tid] = 0.f; cQ[tid] = 0.f; }
        __syncthreads();
        atomicAdd(&cS[col], s);
        atomicAdd(&cQ[col], q);
        __syncthreads();
        if (tid < 64) {
            atomicAdd(&g_bnsum[slayer][col0 + tid], cS[tid]);
            atomicAdd(&g_bnsq[slayer][col0 + tid], cQ[tid]);
        }
    } else {
        __half2* oh = (__half2*)out_h;
        int d2 = dout >> 1;
#pragma unroll
        for (int idx = tid; idx < 64 * 32; idx += 256) {
            int r = idx >> 5, c2 = idx & 31;
            float v0 = buf[r * LDB + 2 * c2];
            float v1 = buf[r * LDB + 2 * c2 + 1];
            oh[(size_t)(row0 + r) * d2 + (col0 >> 1) + c2] = __floats2half2_rn(v0, v1);
        }
        if (EPI == 2) {
            int row = tid & 63;
            int part = tid >> 6;
            int c0 = part * 16;
            int C = dout >> 2;
            int hh = (col0 + c0) / C;
            float s1 = 0.f, s2 = 0.f;
#pragma unroll
            for (int c = c0; c < c0 + 16; c++) {
                float v = buf[row * LDB + c];
                s1 += v * av_src[col0 + c];
                s2 += v * av_dst[col0 + c];
            }
            __shared__ float sA[64][4], sD[64][4];
            sA[tid >> 2][tid & 3] = 0.f;
            sD[tid >> 2][tid & 3] = 0.f;
            __syncthreads();
            atomicAdd(&sA[row][hh], s1);
            atomicAdd(&sD[row][hh], s2);
            __syncthreads();
            int hlo = col0 / C;
            int hcnt = 64 / C;
            if (tid < 64 * hcnt) {
                int r = tid / hcnt, k = tid % hcnt;
                int grow = row0 + r;
                if (grow < n) {
                    g_an_src[grow * 4 + hlo + k] = sA[r][hlo + k];
                    g_an_dst[grow * 4 + hlo + k] = sD[r][hlo + k];
                }
            }
        }
    }
}

// ---------------- pre-aggregation @16: warp/node, half-warp/edge ------------
__global__ void pre_agg16_w(const float* __restrict__ x, float* __restrict__ z) {
    int gw = (blockIdx.x * blockDim.x + threadIdx.x) >> 5;
    if (gw >= NN) return;
    int i = gw;
    int lane = threadIdx.x & 31;
    int half = lane >> 4;
    int col = lane & 15;
    float di = g_dis[i];
    float acc = (half == 0) ? x[(size_t)i * 16 + col] * di * di : 0.f;
    int s = g_offs[i], end = s + g_cnt[i];
    int e = s + half;
    for (; e + 2 < end; e += 4) {
        int j0 = g_csrc[e], j1 = g_csrc[e + 2];
        float w0 = g_ew[e], w1 = g_ew[e + 2];
        acc += x[(size_t)j0 * 16 + col] * w0 + x[(size_t)j1 * 16 + col] * w1;
    }
    if (e < end)
        acc += x[(size_t)g_csrc[e] * 16 + col] * g_ew[e];
    acc += __shfl_xor_sync(0xffffffffu, acc, 16);
    if (half == 0)
        z[(size_t)i * 16 + col] = acc;
}

// ---------------- pre-agg @64 (half input), ew, 4-unroll --------------------
__global__ void pre_agg64_h(const __half2* __restrict__ x2, float* __restrict__ z) {
    int gw = (blockIdx.x * blockDim.x + threadIdx.x) >> 5;
    int lane = threadIdx.x & 31;
    if (gw >= NN) return;
    int i = gw;
    float di = g_dis[i], ws = di * di;
    float2 hv = __half22float2(x2[(size_t)i * 32 + lane]);
    float a0 = hv.x * ws, a1 = hv.y * ws;
    int e = g_offs[i], end = e + g_cnt[i];
    for (; e + 3 < end; e += 4) {
        int j0 = g_csrc[e], j1 = g_csrc[e + 1], j2 = g_csrc[e + 2], j3 = g_csrc[e + 3];
        float w0 = g_ew[e], w1 = g_ew[e + 1], w2 = g_ew[e + 2], w3 = g_ew[e + 3];
        float2 v0 = __half22float2(x2[(size_t)j0 * 32 + lane]);
        float2 v1 = __half22float2(x2[(size_t)j1 * 32 + lane]);
        float2 v2 = __half22float2(x2[(size_t)j2 * 32 + lane]);
        float2 v3 = __half22float2(x2[(size_t)j3 * 32 + lane]);
        a0 += v0.x * w0 + v1.x * w1 + v2.x * w2 + v3.x * w3;
        a1 += v0.y * w0 + v1.y * w1 + v2.y * w2 + v3.y * w3;
    }
    for (; e < end; e++) {
        int j = g_csrc[e];
        float w = g_ew[e];
        float2 v = __half22float2(x2[(size_t)j * 32 + lane]);
        a0 += v.x * w;
        a1 += v.y * w;
    }
    *(float2*)&z[(size_t)i * 64 + 2 * lane] = make_float2(a0, a1);
}

// ---------------- GCN post-agg @128 (half gather, ew, 4-unroll) + stats -----
__global__ void gcn_agg128_h(const __half2* __restrict__ h2, const float* __restrict__ bias,
                             float* __restrict__ y, int layer) {
    __shared__ float sS[128], sQ[128];
    int tid = threadIdx.x;
    for (int t = tid; t < 128; t += blockDim.x) { sS[t] = 0.f; sQ[t] = 0.f; }
    __syncthreads();
    int lane = tid & 31;
    int gw = (blockIdx.x * blockDim.x + tid) >> 5;
    int nw = (gridDim.x * blockDim.x) >> 5;
    float b0[2], b1[2];
#pragma unroll
    for (int cc = 0; cc < 2; cc++) {
        int col = cc * 64 + 2 * lane;
        b0[cc] = bias[col]; b1[cc] = bias[col + 1];
    }
    float s0[2] = {0.f, 0.f}, s1[2] = {0.f, 0.f}, q0[2] = {0.f, 0.f}, q1[2] = {0.f, 0.f};

    for (int i = gw; i < NN; i += nw) {
        float di = g_dis[i];
        float ws = di * di;
        float a0[2], a1[2];
#pragma unroll
        for (int cc = 0; cc < 2; cc++) {
            float2 v = __half22float2(h2[(size_t)i * 64 + cc * 32 + lane]);
            a0[cc] = v.x * ws; a1[cc] = v.y * ws;
        }
        int e = g_offs[i];
        int end = e + g_cnt[i];
        for (; e + 3 < end; e += 4) {
            int j0 = g_csrc[e], j1 = g_csrc[e + 1], j2 = g_csrc[e + 2], j3 = g_csrc[e + 3];
            float w0 = g_ew[e], w1 = g_ew[e + 1], w2 = g_ew[e + 2], w3 = g_ew[e + 3];
#pragma unroll
            for (int cc = 0; cc < 2; cc++) {
                float2 v0 = __half22float2(h2[(size_t)j0 * 64 + cc * 32 + lane]);
                float2 v1 = __half22float2(h2[(size_t)j1 * 64 + cc * 32 + lane]);
                float2 v2 = __half22float2(h2[(size_t)j2 * 64 + cc * 32 + lane]);
                float2 v3 = __half22float2(h2[(size_t)j3 * 64 + cc * 32 + lane]);
                a0[cc] += v0.x * w0 + v1.x * w1 + v2.x * w2 + v3.x * w3;
                a1[cc] += v0.y * w0 + v1.y * w1 + v2.y * w2 + v3.y * w3;
            }
        }
        for (; e < end; e++) {
            int j = g_csrc[e];
            float w = g_ew[e];
#pragma unroll
            for (int cc = 0; cc < 2; cc++) {
                float2 v = __half22float2(h2[(size_t)j * 64 + cc * 32 + lane]);
                a0[cc] += v.x * w;
                a1[cc] += v.y * w;
            }
        }
#pragma unroll
        for (int cc = 0; cc < 2; cc++) {
            float v0 = a0[cc] + b0[cc];
            float v1 = a1[cc] + b1[cc];
            int col = cc * 64 + 2 * lane;
            *(float2*)&y[(size_t)i * 128 + col] = make_float2(v0, v1);
            s0[cc] += v0; q0[cc] += v0 * v0;
            s1[cc] += v1; q1[cc] += v1 * v1;
        }
    }
#pragma unroll
    for (int cc = 0; cc < 2; cc++) {
        int col = cc * 64 + 2 * lane;
        atomicAdd(&sS[col], s0[cc]);
        atomicAdd(&sQ[col], q0[cc]);
        atomicAdd(&sS[col + 1], s1[cc]);
        atomicAdd(&sQ[col + 1], q1[cc]);
    }
    __syncthreads();
    for (int t = tid; t < 128; t += blockDim.x) {
        atomicAdd(&g_bnsum[layer][t], sS[t]);
        atomicAdd(&g_bnsq[layer][t], sQ[t]);
    }
}

// ---------------- GCN post-agg @64 fused with pooling + stats ---------------
__global__ void gcn_pool_h(const __half2* __restrict__ h2, const float* __restrict__ bias,
                           const int* __restrict__ batch, int layer) {
    __shared__ float sS[64], sQ[64];
    int tid = threadIdx.x;
    for (int t = tid; t < 64; t += blockDim.x) { sS[t] = 0.f; sQ[t] = 0.f; }
    __syncthreads();
    int lane = tid & 31;
    int gw = (blockIdx.x * blockDim.x + tid) >> 5;
    int nw = (gridDim.x * blockDim.x) >> 5;
    int col = 2 * lane;
    float b0 = bias[col], b1 = bias[col + 1];
    float s0 = 0.f, s1 = 0.f, q0 = 0.f, q1 = 0.f;

    for (int i = gw; i < NN; i += nw) {
        float di = g_dis[i];
        float ws = di * di;
        float2 hv = __half22float2(h2[(size_t)i * 32 + lane]);
        float a0 = hv.x * ws, a1 = hv.y * ws;
        int e = g_offs[i];
        int end = e + g_cnt[i];
        for (; e + 3 < end; e += 4) {
            int j0 = g_csrc[e], j1 = g_csrc[e + 1], j2 = g_csrc[e + 2], j3 = g_csrc[e + 3];
            float w0 = g_ew[e], w1 = g_ew[e + 1], w2 = g_ew[e + 2], w3 = g_ew[e + 3];
            float2 v0 = __half22float2(h2[(size_t)j0 * 32 + lane]);
            float2 v1 = __half22float2(h2[(size_t)j1 * 32 + lane]);
            float2 v2 = __half22float2(h2[(size_t)j2 * 32 + lane]);
            float2 v3 = __half22float2(h2[(size_t)j3 * 32 + lane]);
            a0 += v0.x * w0 + v1.x * w1 + v2.x * w2 + v3.x * w3;
            a1 += v0.y * w0 + v1.y * w1 + v2.y * w2 + v3.y * w3;
        }
        for (; e < end; e++) {
            int j = g_csrc[e];
            float w = g_ew[e];
            float2 v = __half22float2(h2[(size_t)j * 32 + lane]);
            a0 += v.x * w;
            a1 += v.y * w;
        }
        float v0 = a0 + b0;
        float v1 = a1 + b1;
        int gph = batch[i] * 64 + col;
        atomicAdd(&g_pool[gph], v0);
        atomicAdd(&g_pool[gph + 1], v1);
        s0 += v0; q0 += v0 * v0;
        s1 += v1; q1 += v1 * v1;
    }
    atomicAdd(&sS[col], s0);
    atomicAdd(&sQ[col], q0);
    atomicAdd(&sS[col + 1], s1);
    atomicAdd(&sQ[col + 1], q1);
    __syncthreads();
    for (int t = tid; t < 64; t += blockDim.x) {
        atomicAdd(&g_bnsum[layer][t], sS[t]);
        atomicAdd(&g_bnsq[layer][t], sQ[t]);
    }
}

// ---------------- GAT aggregation: single-pass, lane-parallel logits --------
// OUTH=1: half2 output; OUTH=0: fp32 output
template <int DOUT, int OUTH>
__global__ void gat_agg_h(const __half2* __restrict__ hg2, const float* __restrict__ yres,
                          const float* __restrict__ bias,
                          float* __restrict__ xout, __half2* __restrict__ xout_h,
                          const float* __restrict__ bng, const float* __restrict__ bnb,
                          int layer) {
    constexpr int CC = DOUT / 64;
    constexpr int D2 = DOUT / 2;
    constexpr int C = DOUT / 4;
    __shared__ int    sj[8][32];
    __shared__ float4 sq[8][32];
    int gw = (blockIdx.x * blockDim.x + threadIdx.x) >> 5;
    int lane = threadIdx.x & 31;
    int w = (threadIdx.x >> 5);
    if (gw >= NN) return;
    int i = gw;
    float4 asi = *(const float4*)&g_an_src[i * 4];
    float4 adi = *(const float4*)&g_an_dst[i * 4];
    // self logit (no max shift: logits are O(1) for this model)
    float p0 = __expf(lrelu(asi.x + adi.x));
    float p1 = __expf(lrelu(asi.y + adi.y));
    float p2 = __expf(lrelu(asi.z + adi.z));
    float p3 = __expf(lrelu(asi.w + adi.w));
    int hh[CC];
    float a0[CC], a1[CC];
#pragma unroll
    for (int cc = 0; cc < CC; cc++) {
        int col = cc * 64 + 2 * lane;
        hh[cc] = col / C;
        float p = hh[cc] == 0 ? p0 : hh[cc] == 1 ? p1 : hh[cc] == 2 ? p2 : p3;
        float2 hv = __half22float2(hg2[(size_t)i * D2 + cc * 32 + lane]);
        a0[cc] = hv.x * p;
        a1[cc] = hv.y * p;
    }
    float d0 = 0.f, d1 = 0.f, d2 = 0.f, d3 = 0.f;  // lane-partial denominators
    int s = g_offs[i], end = s + g_cnt[i];
    for (int base = s; base < end; base += 32) {
        int e = base + lane;
        float4 qv = make_float4(0.f, 0.f, 0.f, 0.f);
        int j = 0;
        if (e < end) {
            j = g_csrc[e];
            float4 aj = *(const float4*)&g_an_src[j * 4];
            qv.x = __expf(lrelu(aj.x + adi.x));
            qv.y = __expf(lrelu(aj.y + adi.y));
            qv.z = __expf(lrelu(aj.z + adi.z));
            qv.w = __expf(lrelu(aj.w + adi.w));
            d0 += qv.x; d1 += qv.y; d2 += qv.z; d3 += qv.w;
        }
        sj[w][lane] = j;
        sq[w][lane] = qv;
        __syncwarp();
        int m = min(32, end - base);
        int k = 0;
        for (; k + 1 < m; k += 2) {
            int j0 = sj[w][k], j1 = sj[w][k + 1];
#pragma unroll
            for (int cc = 0; cc < CC; cc++) {
                float qa = ((const float*)&sq[w][k])[hh[cc]];
                float qb = ((const float*)&sq[w][k + 1])[hh[cc]];
                float2 v0 = __half22float2(hg2[(size_t)j0 * D2 + cc * 32 + lane]);
                float2 v1 = __half22float2(hg2[(size_t)j1 * D2 + cc * 32 + lane]);
                a0[cc] += v0.x * qa + v1.x * qb;
                a1[cc] += v0.y * qa + v1.y * qb;
            }
        }
        if (k < m) {
            int j0 = sj[w][k];
#pragma unroll
            for (int cc = 0; cc < CC; cc++) {
                float qa = ((const float*)&sq[w][k])[hh[cc]];
                float2 v0 = __half22float2(hg2[(size_t)j0 * D2 + cc * 32 + lane]);
                a0[cc] += v0.x * qa;
                a1[cc] += v0.y * qa;
            }
        }
        __syncwarp();
    }
    // reduce lane-partial denominators; add self
#pragma unroll
    for (int off = 16; off > 0; off >>= 1) {
        d0 += __shfl_xor_sync(0xffffffffu, d0, off);
        d1 += __shfl_xor_sync(0xffffffffu, d1, off);
        d2 += __shfl_xor_sync(0xffffffffu, d2, off);
        d3 += __shfl_xor_sync(0xffffffffu, d3, off);
    }
    d0 += p0; d1 += p1; d2 += p2; d3 += p3;
#pragma unroll
    for (int cc = 0; cc < CC; cc++) {
        float d = hh[cc] == 0 ? d0 : hh[cc] == 1 ? d1 : hh[cc] == 2 ? d2 : d3;
        int col = cc * 64 + 2 * lane;
        float sc0, sf0, sc1, sf1;
        bn_affine(layer, col, bng, bnb, sc0, sf0);
        bn_affine(layer, col + 1, bng, bnb, sc1, sf1);
        float2 rv = *(const float2*)&yres[(size_t)i * DOUT + col];
        float v0 = lrelu(a0[cc] / d + bias[col] + rv.x * sc0 + sf0);
        float v1 = lrelu(a1[cc] / d + bias[col + 1] + rv.y * sc1 + sf1);
        if (OUTH)
            xout_h[(size_t)i * D2 + cc * 32 + lane] = __floats2half2_rn(v0, v1);
        else
            *(float2*)&xout[(size_t)i * DOUT + col] = make_float2(v0, v1);
    }
}

// ---------------- pooling finalize (raw-sum pooling + BN affine) ------------
__global__ void pool_fin(float* __restrict__ out,
                         const float* __restrict__ bng, const float* __restrict__ bnb) {
    int i = blockIdx.x * blockDim.x + threadIdx.x;
    if (i < GG * 64) {
        int g = i >> 6, c = i & 63;
        float scv, shf;
        bn_affine(3, c, bng, bnb, scv, shf);
        float cnt = g_pcnt[g];
        out[i] = (g_pool[i] * scv + shf * cnt) / fmaxf(cnt, 1.f);
    }
}

// ---------------- host orchestration --------------------------------------
extern "C" void kernel_launch(void* const* d_in, const int* in_sizes, int n_in,
                              void* d_out, int out_size) {
    const float* x_in = (const float*)d_in[0];
    const int* ei = (const int*)d_in[1];
    const int* batch = (const int*)d_in[2];

    const float* gcn_w[4] = {(const float*)d_in[3], (const float*)d_in[7],
                             (const float*)d_in[11], (const float*)d_in[15]};
    const float* gcn_b[4] = {(const float*)d_in[4], (const float*)d_in[8],
                             (const float*)d_in[12], (const float*)d_in[16]};
    const float* bn_g[4] = {(const float*)d_in[5], (const float*)d_in[9],
                            (const float*)d_in[13], (const float*)d_in[17]};
    const float* bn_b[4] = {(const float*)d_in[6], (const float*)d_in[10],
                            (const float*)d_in[14], (const float*)d_in[18]};
    const float* gat_w[2] = {(const float*)d_in[19], (const float*)d_in[23]};
    const float* gat_as[2] = {(const float*)d_in[20], (const float*)d_in[24]};
    const float* gat_ad[2] = {(const float*)d_in[21], (const float*)d_in[25]};
    const float* gat_b[2] = {(const float*)d_in[22], (const float*)d_in[26]};

    float *px, *py, *ph;
    __half *phh, *phgh, *pxh;
    cudaGetSymbolAddress((void**)&px, g_x);
    cudaGetSymbolAddress((void**)&py, g_y);
    cudaGetSymbolAddress((void**)&ph, g_h);
    cudaGetSymbolAddress((void**)&phh, g_hh);
    cudaGetSymbolAddress((void**)&phgh, g_hgh);
    cudaGetSymbolAddress((void**)&pxh, g_xh);

    const int warp_blocks = (NN * 32 + 255) / 256;
    const int agg_blocks = 148 * 8;
    const dim3 g1((NPAD + 63) / 64, 1);
    const dim3 g2((NPAD + 63) / 64, 2);

    // ---- CSR build ----
    zero_init<<<256, 256>>>();
    hist_k<<<1024, 256>>>(ei + EE, batch);
    scan1<<<NB_SCAN, 1024>>>();
    scan3_dis<<<NB_SCAN, 1024>>>();
    scatter_k<<<1024, 256>>>(ei, ei + EE);

    // ---- layer 0: pre-agg @16, GEMM 16->64 (+bias+stats L0), GAT ----
    pre_agg16_w<<<warp_blocks, 256>>>(x_in, ph);
    gemm_tf32<0, 1><<<g1, 256>>>(ph, gcn_w[0], py, nullptr, NN, 16, 64,
                                 nullptr, nullptr, 0, gcn_b[0], 0, nullptr, nullptr);
    gemm_tf32<1, 2><<<g1, 256>>>(py, gat_w[0], nullptr, phgh, NN, 64, 64,
                                 bn_g[0], bn_b[0], 0, nullptr, 0, gat_as[0], gat_ad[0]);
    gat_agg_h<64, 1><<<warp_blocks, 256>>>((const __half2*)phgh, py, gat_b[0],
                                           nullptr, (__half2*)pxh,
                                           bn_g[0], bn_b[0], 0);

    // ---- layer 1: pre-agg @64, GEMM 64->128 (+bias+stats L1) ----
    pre_agg64_h<<<warp_blocks, 256>>>((const __half2*)pxh, ph);
    gemm_tf32<0, 1><<<g2, 256>>>(ph, gcn_w[1], py, nullptr, NN, 64, 128,
                                 nullptr, nullptr, 0, gcn_b[1], 1, nullptr, nullptr);

    // ---- layer 2: GEMM(BN1+lrelu) 128->128 -> half, post-agg, GAT ----
    gemm_tf32<2, 3><<<g2, 256>>>(py, gcn_w[2], nullptr, phh, NN, 128, 128,
                                 bn_g[1], bn_b[1], 1, nullptr, 0, nullptr, nullptr);
    gcn_agg128_h<<<agg_blocks, 256>>>((const __half2*)phh, gcn_b[2], py, 2);
    gemm_tf32<1, 2><<<g2, 256>>>(py, gat_w[1], nullptr, phgh, NN, 128, 128,
                                 bn_g[2], bn_b[2], 2, nullptr, 0, gat_as[1], gat_ad[1]);
    gat_agg_h<128, 0><<<warp_blocks, 256>>>((const __half2*)phgh, py, gat_b[1],
                                            px, nullptr, bn_g[2], bn_b[2], 2);

    // ---- layer 3: GEMM 128->64 -> half, post-agg @64 + pooling fused ----
    gemm_tf32<0, 3><<<g1, 256>>>(px, gcn_w[3], nullptr, phh, NN, 128, 64,
                                 nullptr, nullptr, 0, nullptr, 0, nullptr, nullptr);
    gcn_pool_h<<<agg_blocks, 256>>>((const __half2*)phh, gcn_b[3], batch, 3);

    // ---- finalize pooled means (BN3 affine on raw sums) ----
    pool_fin<<<(GG * 64 + 255) / 256, 256>>>((float*)d_out, bn_g[3], bn_b[3]);
}